// round 2
// baseline (speedup 1.0000x reference)
#include <cuda_runtime.h>
#include <math.h>

// Problem constants
#define NN 4096
#define FF 64
#define OO 64
#define KK 5
#define BB 8

// ---------------------------------------------------------------------------
// Scratch layout (single __device__ global array; ~126.6 MB)
// ---------------------------------------------------------------------------
#define OFF_C1    0L           // [B][N][128]: cols 0..63 = tx0 = featc@W, cols 64..127 = nan mask
#define OFF_G1    4194304L     // [B][N][128]: shift @ C1  -> cols 0..63 = cx0, 64..127 = S
#define OFF_G2    8388608L     // [B][N][64] : A2 @ mask   -> T
#define OFF_DX    10485760L    // [B][K][N][64]: S @ (mu_k * W)
#define OFF_DC    20971520L    // [B][K][N][64]: T @ (var_k * W^2)
#define OFF_M     31457280L    // [K][64][64]: mu[k,f]*W[f,o]
#define OFF_V     31477760L    // [K][64][64]: exp(sigma[k,f])*W[f,o]^2
#define OFF_GAMMA 31498240L    // [B][N][K]: softmax responsibilities
#define SCRATCH_TOTAL 31662080L

__device__ float g_scratch[SCRATCH_TOTAL];

// ---------------------------------------------------------------------------
// P0: build per-component matrices M_k = mu_k * W, V_k = var_k * W^2
// ---------------------------------------------------------------------------
__global__ void prep_mv_kernel(const float* __restrict__ W,
                               const float* __restrict__ mu,
                               const float* __restrict__ sigma) {
    int idx = blockIdx.x * 256 + threadIdx.x;
    if (idx >= KK * 64 * 64) return;
    int k = idx >> 12;
    int f = (idx >> 6) & 63;
    int o = idx & 63;
    float w = W[f * 64 + o];
    g_scratch[OFF_M + idx] = mu[k * 64 + f] * w;
    g_scratch[OFF_V + idx] = expf(sigma[k * 64 + f]) * w * w;
}

// ---------------------------------------------------------------------------
// P1: per-row prep. One warp per (b,n) row:
//   - nan mask + sanitized features
//   - tx0 = featc @ W        (C1 cols 0..63)
//   - mask                   (C1 cols 64..127)
//   - gamma = softmax_k(pi_k - 0.5 * sum_{f not nan} (x-mu)^2/var)
// ---------------------------------------------------------------------------
__global__ void __launch_bounds__(256) prep_rows_kernel(
    const float* __restrict__ feat, const float* __restrict__ W,
    const float* __restrict__ mu, const float* __restrict__ sigma,
    const float* __restrict__ pi)
{
    __shared__ float Ws[64 * 64];
    __shared__ float mus[KK * 64];
    __shared__ float ivs[KK * 64];
    __shared__ float pis[KK];
    __shared__ float fbuf[8][64];

    int tid = threadIdx.x;
    for (int i = tid; i < 64 * 64; i += 256) Ws[i] = W[i];
    for (int i = tid; i < KK * 64; i += 256) {
        mus[i] = mu[i];
        ivs[i] = expf(-sigma[i]);   // 1/var
    }
    if (tid < KK) pis[tid] = pi[tid];
    __syncthreads();

    int warp = tid >> 5, lane = tid & 31;
    long row = (long)blockIdx.x * 8 + warp;   // row in [0, B*N)
    const float* fr = feat + row * 64;
    float* c1p = g_scratch + OFF_C1 + row * 128;

    float v0 = fr[lane], v1 = fr[lane + 32];
    bool  nm0 = isnan(v0), nm1 = isnan(v1);
    float f0 = nm0 ? 0.f : v0;
    float f1 = nm1 ? 0.f : v1;
    fbuf[warp][lane] = f0;
    fbuf[warp][lane + 32] = f1;
    c1p[64 + lane]      = nm0 ? 1.f : 0.f;
    c1p[64 + lane + 32] = nm1 ? 1.f : 0.f;
    __syncwarp();

    // tx0 = featc @ W: each lane computes 2 outputs
    #pragma unroll 1
    for (int oo = 0; oo < 2; oo++) {
        int o = lane + oo * 32;
        float s = 0.f;
        #pragma unroll
        for (int f = 0; f < 64; f++) s = fmaf(fbuf[warp][f], Ws[f * 64 + o], s);
        c1p[o] = s;
    }

    // responsibilities (constants cancel in softmax over k)
    float lg[KK];
    #pragma unroll
    for (int k = 0; k < KK; k++) {
        float p = 0.f;
        if (!nm0) { float d = f0 - mus[k * 64 + lane];      p = fmaf(d * d, ivs[k * 64 + lane], p); }
        if (!nm1) { float d = f1 - mus[k * 64 + lane + 32]; p = fmaf(d * d, ivs[k * 64 + lane + 32], p); }
        #pragma unroll
        for (int off = 16; off > 0; off >>= 1) p += __shfl_xor_sync(0xffffffffu, p, off);
        lg[k] = pis[k] - 0.5f * p;
    }
    float mx = lg[0];
    #pragma unroll
    for (int k = 1; k < KK; k++) mx = fmaxf(mx, lg[k]);
    float e[KK], den = 0.f;
    #pragma unroll
    for (int k = 0; k < KK; k++) { e[k] = expf(lg[k] - mx); den += e[k]; }
    if (lane == 0) {
        float inv = 1.f / den;
        #pragma unroll
        for (int k = 0; k < KK; k++) g_scratch[OFF_GAMMA + row * KK + k] = e[k] * inv;
    }
}

// ---------------------------------------------------------------------------
// Tiled batched SGEMM: C[z] = A[z/aDiv] @ B[z%bMod]
// A row-major [M x Kd] (lda), B row-major [Kd x Nc] (ldb), C row-major (ldc).
// All tile dims divide problem dims exactly (asserted by launch configs).
// ---------------------------------------------------------------------------
template<int BM, int BN, int BK, int TM, int TN>
__global__ void __launch_bounds__((BM / TM) * (BN / TN), 2)
sgemm_batched(const float* __restrict__ A, const float* __restrict__ Bm,
              float* __restrict__ C, int Kd, int lda, int ldb, int ldc,
              long aStride, int aDiv, long bStride, int bMod, long cStride)
{
    constexpr int THREADS = (BM / TM) * (BN / TN);
    constexpr int AF4 = BM * BK / 4;
    constexpr int BF4 = BK * BN / 4;
    constexpr int AP = (AF4 + THREADS - 1) / THREADS;
    constexpr int BP = (BF4 + THREADS - 1) / THREADS;

    const int z = blockIdx.z;
    const float* Ab = A + (long)(z / aDiv) * aStride;
    const float* Bb = Bm + (long)(z % bMod) * bStride;
    float* Cb = C + (long)z * cStride;

    const int m0 = blockIdx.y * BM;
    const int n0 = blockIdx.x * BN;

    __shared__ float As[BK][BM];
    __shared__ float Bs[BK][BN];

    const int tid = threadIdx.x;
    const int tx = tid % (BN / TN);
    const int ty = tid / (BN / TN);

    float acc[TM][TN] = {};
    float4 aReg[AP], bReg[BP];

    auto loadA = [&](int kt) {
        #pragma unroll
        for (int p = 0; p < AP; p++) {
            int idx = tid + p * THREADS;
            if (AF4 % THREADS == 0 || idx < AF4) {
                int r = idx / (BK / 4);
                int c = idx % (BK / 4);
                aReg[p] = *(const float4*)(Ab + (long)(m0 + r) * lda + kt + c * 4);
            }
        }
    };
    auto loadB = [&](int kt) {
        #pragma unroll
        for (int p = 0; p < BP; p++) {
            int idx = tid + p * THREADS;
            if (BF4 % THREADS == 0 || idx < BF4) {
                int r = idx / (BN / 4);
                int c = idx % (BN / 4);
                bReg[p] = *(const float4*)(Bb + (long)(kt + r) * ldb + n0 + c * 4);
            }
        }
    };
    auto storeA = [&]() {
        #pragma unroll
        for (int p = 0; p < AP; p++) {
            int idx = tid + p * THREADS;
            if (AF4 % THREADS == 0 || idx < AF4) {
                int r = idx / (BK / 4);
                int c = idx % (BK / 4);
                As[c * 4 + 0][r] = aReg[p].x;
                As[c * 4 + 1][r] = aReg[p].y;
                As[c * 4 + 2][r] = aReg[p].z;
                As[c * 4 + 3][r] = aReg[p].w;
            }
        }
    };
    auto storeB = [&]() {
        #pragma unroll
        for (int p = 0; p < BP; p++) {
            int idx = tid + p * THREADS;
            if (BF4 % THREADS == 0 || idx < BF4) {
                int r = idx / (BN / 4);
                int c = idx % (BN / 4);
                *(float4*)(&Bs[r][c * 4]) = bReg[p];
            }
        }
    };

    loadA(0); loadB(0);
    storeA(); storeB();
    __syncthreads();

    for (int kt = 0; kt < Kd; kt += BK) {
        bool more = (kt + BK) < Kd;
        if (more) { loadA(kt + BK); loadB(kt + BK); }
        #pragma unroll
        for (int kk = 0; kk < BK; kk++) {
            float af[TM], bf[TN];
            #pragma unroll
            for (int i = 0; i < TM; i++) af[i] = As[kk][ty * TM + i];
            #pragma unroll
            for (int j = 0; j < TN; j++) bf[j] = Bs[kk][tx * TN + j];
            #pragma unroll
            for (int i = 0; i < TM; i++)
                #pragma unroll
                for (int j = 0; j < TN; j++)
                    acc[i][j] = fmaf(af[i], bf[j], acc[i][j]);
        }
        __syncthreads();
        if (more) { storeA(); storeB(); __syncthreads(); }
    }

    #pragma unroll
    for (int i = 0; i < TM; i++) {
        float* cr = Cb + (long)(m0 + ty * TM + i) * ldc + n0 + tx * TN;
        #pragma unroll
        for (int j = 0; j < TN; j += 4) {
            *(float4*)(cr + j) = make_float4(acc[i][j], acc[i][j + 1],
                                             acc[i][j + 2], acc[i][j + 3]);
        }
    }
}

// ---------------------------------------------------------------------------
// Epilogue: out[b,n,o] = sum_k gamma[b,n,k] * E[ReLU(N(cx0+Dx, Dc))]
// ---------------------------------------------------------------------------
__global__ void __launch_bounds__(256) epilogue_kernel(float* __restrict__ out) {
    long idx = (long)blockIdx.x * 256 + threadIdx.x;   // < B*N*64
    long row = idx >> 6;
    int o = (int)(idx & 63);
    int b = (int)(row >> 12);
    int n = (int)(row & 4095);

    float cx0 = g_scratch[OFF_G1 + row * 128 + o];
    const float* gam = g_scratch + OFF_GAMMA + row * KK;

    float acc = 0.f;
    #pragma unroll
    for (int k = 0; k < KK; k++) {
        long zoff = ((long)(b * KK + k) << 18) + ((long)n << 6) + o;
        float mean = cx0 + g_scratch[OFF_DX + zoff];
        float var  = g_scratch[OFF_DC + zoff];
        float ex;
        float sd = sqrtf(fmaxf(var, 0.f));
        if (sd > 0.f) {
            float zz  = mean / sd;
            float pdf = expf(-0.5f * zz * zz) * 0.3989422804014327f;
            float cdf = 0.5f * (1.f + erff(zz * 0.7071067811865476f));
            ex = mean * cdf + sd * pdf;
        } else {
            ex = fmaxf(mean, 0.f);
        }
        acc = fmaf(gam[k], ex, acc);
    }
    out[idx] = acc;
}

// ---------------------------------------------------------------------------
// Launch
// ---------------------------------------------------------------------------
extern "C" void kernel_launch(void* const* d_in, const int* in_sizes, int n_in,
                              void* d_out, int out_size) {
    const float* shift = (const float*)d_in[0];
    const float* A2    = (const float*)d_in[1];
    const float* feat  = (const float*)d_in[2];
    const float* W     = (const float*)d_in[3];
    const float* pi    = (const float*)d_in[4];
    const float* mu    = (const float*)d_in[5];
    const float* sigma = (const float*)d_in[6];
    float* out = (float*)d_out;

    float* scr = nullptr;
    cudaGetSymbolAddress((void**)&scr, g_scratch);

    // P0 + P1
    prep_mv_kernel<<<(KK * 64 * 64 + 255) / 256, 256>>>(W, mu, sigma);
    prep_rows_kernel<<<BB * NN / 8, 256>>>(feat, W, mu, sigma, pi);

    // G1 = shift @ [tx0 | mask]   (per b):  [4096x4096] @ [4096x128]
    sgemm_batched<128, 128, 8, 8, 8><<<dim3(1, NN / 128, BB), 256>>>(
        shift, scr + OFF_C1, scr + OFF_G1,
        /*Kd=*/NN, /*lda=*/NN, /*ldb=*/128, /*ldc=*/128,
        /*aStride=*/0L, /*aDiv=*/1, /*bStride=*/(long)NN * 128, /*bMod=*/BB,
        /*cStride=*/(long)NN * 128);

    // G2 = A2 @ mask   (per b):  [4096x4096] @ [4096x64]
    sgemm_batched<128, 64, 8, 8, 4><<<dim3(1, NN / 128, BB), 256>>>(
        A2, scr + OFF_C1 + 64, scr + OFF_G2,
        NN, NN, 128, 64,
        0L, 1, (long)NN * 128, BB,
        (long)NN * 64);

    // Dx[b,k] = S[b] @ M_k :  [4096x64] @ [64x64], z = b*K+k
    sgemm_batched<128, 64, 8, 8, 4><<<dim3(1, NN / 128, BB * KK), 256>>>(
        scr + OFF_G1 + 64, scr + OFF_M, scr + OFF_DX,
        64, 128, 64, 64,
        (long)NN * 128, KK, 4096L, KK,
        (long)NN * 64);

    // Dc[b,k] = T[b] @ V_k :  [4096x64] @ [64x64]
    sgemm_batched<128, 64, 8, 8, 4><<<dim3(1, NN / 128, BB * KK), 256>>>(
        scr + OFF_G2, scr + OFF_V, scr + OFF_DC,
        64, 64, 64, 64,
        (long)NN * 64, KK, 4096L, KK,
        (long)NN * 64);

    // fused ex_relu + mixture epilogue
    epilogue_kernel<<<BB * NN * 64 / 256, 256>>>(out);
}

// round 4
// speedup vs baseline: 2.8663x; 2.8663x over previous
#include <cuda_runtime.h>
#include <cuda_bf16.h>
#include <cstdint>
#include <math.h>

// Problem constants
#define NN 4096
#define FF 64
#define OO 64
#define KK 5
#define BB 8

// ---------------------------------------------------------------------------
// Scratch layout (single __device__ global array)
// ---------------------------------------------------------------------------
#define OFF_C1       0L           // [B][N][128] fp32: cols 0..63 tx0, 64..127 mask
#define OFF_G1       4194304L     // [B][N][128] fp32: cols 0..63 cx0, 64..127 S
#define OFF_G2       8388608L     // [B][N][64]  fp32: T
#define OFF_DX       10485760L    // [B][K][N][64]
#define OFF_DC       20971520L    // [B][K][N][64]
#define OFF_M        31457280L    // [K][64][64]
#define OFF_V        31477760L    // [K][64][64]
#define OFF_GAMMA    31498240L    // [B][N][K]
#define OFF_SHIFT_HI 31662080L    // bf16[4096*4096]   (8388608 floats)
#define OFF_SHIFT_LO 40050688L    // bf16[4096*4096]
#define OFF_A2BF     48439296L    // bf16[4096*4096]
#define OFF_C1THI    56827904L    // bf16[B][128][4096] (2097152 floats)
#define OFF_C1TLO    58925056L    // bf16[B][64][4096]  (1048576 floats)
#define SCRATCH_TOTAL 59973632L

__device__ float g_scratch[SCRATCH_TOTAL];

// ===========================================================================
// PTX helpers (baseline ISA only: cp.async, ldmatrix, mma.sync)
// ===========================================================================
__device__ __forceinline__ uint32_t smem_to_u32(const void* p) {
    uint32_t a;
    asm("{ .reg .u64 t; cvta.to.shared.u64 t, %1; cvt.u32.u64 %0, t; }"
        : "=r"(a) : "l"(p));
    return a;
}

__device__ __forceinline__ void cp16(uint32_t dst, const void* src) {
    asm volatile("cp.async.cg.shared.global [%0], [%1], 16;"
                 :: "r"(dst), "l"(src) : "memory");
}
#define CP_COMMIT() asm volatile("cp.async.commit_group;" ::: "memory")
#define CP_WAIT2()  asm volatile("cp.async.wait_group 2;" ::: "memory")
#define CP_WAIT1()  asm volatile("cp.async.wait_group 1;" ::: "memory")
#define CP_WAIT0()  asm volatile("cp.async.wait_group 0;" ::: "memory")

__device__ __forceinline__ void ldsm4(uint32_t* f, uint32_t addr) {
    asm volatile("ldmatrix.sync.aligned.m8n8.x4.shared.b16 {%0,%1,%2,%3}, [%4];"
                 : "=r"(f[0]), "=r"(f[1]), "=r"(f[2]), "=r"(f[3]) : "r"(addr));
}

__device__ __forceinline__ void mma_bf16(float* c, const uint32_t* a, const uint32_t* b) {
    asm volatile(
        "mma.sync.aligned.m16n8k16.row.col.f32.bf16.bf16.f32 "
        "{%0,%1,%2,%3}, {%4,%5,%6,%7}, {%8,%9}, {%0,%1,%2,%3};"
        : "+f"(c[0]), "+f"(c[1]), "+f"(c[2]), "+f"(c[3])
        : "r"(a[0]), "r"(a[1]), "r"(a[2]), "r"(a[3]), "r"(b[0]), "r"(b[1]));
}

// SW128 swizzle specialized for 128-byte rows: offset = row*128 + kb (kb < 128)
// SWZ(row*128+kb) = row*128 + (kb ^ ((row&7)<<4))
__device__ __forceinline__ uint32_t swz(int row, int kb) {
    return (uint32_t)(row * 128 + (kb ^ ((row & 7) << 4)));
}

// ===========================================================================
// Conversion: fp32 -> bf16 hi (and lo residual)
// ===========================================================================
__global__ void __launch_bounds__(256) convert_split_kernel(
    const float4* __restrict__ src, uint2* __restrict__ hi,
    uint2* __restrict__ lo, int n4)
{
    int i = blockIdx.x * 256 + threadIdx.x;
    if (i >= n4) return;
    float4 v = src[i];
    __nv_bfloat16 hx = __float2bfloat16(v.x), hy = __float2bfloat16(v.y),
                  hz = __float2bfloat16(v.z), hw = __float2bfloat16(v.w);
    uint2 ho;
    ho.x = ((uint32_t)__bfloat16_as_ushort(hy) << 16) | __bfloat16_as_ushort(hx);
    ho.y = ((uint32_t)__bfloat16_as_ushort(hw) << 16) | __bfloat16_as_ushort(hz);
    hi[i] = ho;
    if (lo) {
        __nv_bfloat16 lx = __float2bfloat16(v.x - __bfloat162float(hx));
        __nv_bfloat16 ly = __float2bfloat16(v.y - __bfloat162float(hy));
        __nv_bfloat16 lz = __float2bfloat16(v.z - __bfloat162float(hz));
        __nv_bfloat16 lw = __float2bfloat16(v.w - __bfloat162float(hw));
        uint2 lv;
        lv.x = ((uint32_t)__bfloat16_as_ushort(ly) << 16) | __bfloat16_as_ushort(lx);
        lv.y = ((uint32_t)__bfloat16_as_ushort(lw) << 16) | __bfloat16_as_ushort(lz);
        lo[i] = lv;
    }
}

// ===========================================================================
// P0: build per-component matrices M_k = mu_k * W, V_k = var_k * W^2
// ===========================================================================
__global__ void prep_mv_kernel(const float* __restrict__ W,
                               const float* __restrict__ mu,
                               const float* __restrict__ sigma) {
    int idx = blockIdx.x * 256 + threadIdx.x;
    if (idx >= KK * 64 * 64) return;
    int k = idx >> 12;
    int f = (idx >> 6) & 63;
    int o = idx & 63;
    float w = W[f * 64 + o];
    g_scratch[OFF_M + idx] = mu[k * 64 + f] * w;
    g_scratch[OFF_V + idx] = expf(sigma[k * 64 + f]) * w * w;
}

// ===========================================================================
// P1: per-row prep (tx0, mask, gamma)
// ===========================================================================
__global__ void __launch_bounds__(256) prep_rows_kernel(
    const float* __restrict__ feat, const float* __restrict__ W,
    const float* __restrict__ mu, const float* __restrict__ sigma,
    const float* __restrict__ pi)
{
    __shared__ float Ws[64 * 64];
    __shared__ float mus[KK * 64];
    __shared__ float ivs[KK * 64];
    __shared__ float pis[KK];
    __shared__ float fbuf[8][64];

    int tid = threadIdx.x;
    for (int i = tid; i < 64 * 64; i += 256) Ws[i] = W[i];
    for (int i = tid; i < KK * 64; i += 256) {
        mus[i] = mu[i];
        ivs[i] = expf(-sigma[i]);
    }
    if (tid < KK) pis[tid] = pi[tid];
    __syncthreads();

    int warp = tid >> 5, lane = tid & 31;
    long row = (long)blockIdx.x * 8 + warp;
    const float* fr = feat + row * 64;
    float* c1p = g_scratch + OFF_C1 + row * 128;

    float v0 = fr[lane], v1 = fr[lane + 32];
    bool  nm0 = isnan(v0), nm1 = isnan(v1);
    float f0 = nm0 ? 0.f : v0;
    float f1 = nm1 ? 0.f : v1;
    fbuf[warp][lane] = f0;
    fbuf[warp][lane + 32] = f1;
    c1p[64 + lane]      = nm0 ? 1.f : 0.f;
    c1p[64 + lane + 32] = nm1 ? 1.f : 0.f;
    __syncwarp();

    #pragma unroll 1
    for (int oo = 0; oo < 2; oo++) {
        int o = lane + oo * 32;
        float s = 0.f;
        #pragma unroll
        for (int f = 0; f < 64; f++) s = fmaf(fbuf[warp][f], Ws[f * 64 + o], s);
        c1p[o] = s;
    }

    float lg[KK];
    #pragma unroll
    for (int k = 0; k < KK; k++) {
        float p = 0.f;
        if (!nm0) { float d = f0 - mus[k * 64 + lane];      p = fmaf(d * d, ivs[k * 64 + lane], p); }
        if (!nm1) { float d = f1 - mus[k * 64 + lane + 32]; p = fmaf(d * d, ivs[k * 64 + lane + 32], p); }
        #pragma unroll
        for (int off = 16; off > 0; off >>= 1) p += __shfl_xor_sync(0xffffffffu, p, off);
        lg[k] = pis[k] - 0.5f * p;
    }
    float mx = lg[0];
    #pragma unroll
    for (int k = 1; k < KK; k++) mx = fmaxf(mx, lg[k]);
    float e[KK], den = 0.f;
    #pragma unroll
    for (int k = 0; k < KK; k++) { e[k] = expf(lg[k] - mx); den += e[k]; }
    if (lane == 0) {
        float inv = 1.f / den;
        #pragma unroll
        for (int k = 0; k < KK; k++) g_scratch[OFF_GAMMA + row * KK + k] = e[k] * inv;
    }
}

// ===========================================================================
// Transpose C1 [b][4096][128] fp32 -> C1T hi bf16 [b][128][4096] (+ lo for c<64)
// ===========================================================================
__global__ void __launch_bounds__(1024) transpose_c1_kernel() {
    __shared__ float t[32][33];
    int b = blockIdx.z;
    int m0 = blockIdx.x * 32, c0 = blockIdx.y * 32;
    int tx = threadIdx.x, ty = threadIdx.y;
    const float* src = g_scratch + OFF_C1 + ((long)b * NN + m0) * 128 + c0;
    t[ty][tx] = src[(long)ty * 128 + tx];
    __syncthreads();
    int c = c0 + ty, m = m0 + tx;
    float v = t[tx][ty];
    __nv_bfloat16 hi = __float2bfloat16(v);
    __nv_bfloat16* dhi = (__nv_bfloat16*)(g_scratch + OFF_C1THI);
    dhi[((long)b * 128 + c) * NN + m] = hi;
    if (c < 64) {
        float lo = v - __bfloat162float(hi);
        __nv_bfloat16* dlo = (__nv_bfloat16*)(g_scratch + OFF_C1TLO);
        dlo[((long)b * 64 + c) * NN + m] = __float2bfloat16(lo);
    }
}

// ===========================================================================
// Warp-MMA GEMM (mma.sync bf16, fp32 acc):
//   C[b] rows [m0,m0+128) = Ahi @ Bhi^T (+ Alo @ Bhi^T + Ahi @ Blo^T if SPLIT)
//   A: [4096][4096] bf16 row-major. Bhi: [NB][4096] bf16 K-major rows.
//   Blo: [64][4096] (applies to C cols 0..63 only).
// ===========================================================================
template<int NB, bool SPLIT>
__global__ void __launch_bounds__(256)
mma_gemm_kernel(const __nv_bfloat16* __restrict__ Ahi,
                const __nv_bfloat16* __restrict__ Alo,
                const __nv_bfloat16* __restrict__ Bhi,
                const __nv_bfloat16* __restrict__ Blo,
                float* __restrict__ C,
                long bBatchStride, long cBatchStride)
{
    constexpr int BK = 64;                    // K per chunk (128 bytes)
    constexpr int NC = NN / BK;               // 64 chunks
    constexpr int STAGES = 3;
    constexpr int OFF_A_T  = 0;               // 128x64 bf16 = 16 KB
    constexpr int OFF_AL_T = 16384;
    constexpr int OFF_B_T  = SPLIT ? 32768 : 16384;
    constexpr int OFF_BL_T = SPLIT ? (32768 + NB * 128) : 0;
    constexpr int STAGE_BYTES = SPLIT ? (32768 + NB * 128 + 8192) : (16384 + NB * 128);
    constexpr int WARPS_M = (NB == 128) ? 4 : 8;
    constexpr int MT = 128 / (WARPS_M * 16);  // m16-tiles per warp (2 or 1)
    constexpr int NT = 8;                     // n8-tiles per warp (64 cols)

    extern __shared__ char smem[];
    uint32_t sbase = smem_to_u32(smem);
    const int tid = threadIdx.x, wid = tid >> 5, lane = tid & 31;
    const int wm = wid % WARPS_M, wn = wid / WARPS_M;
    const int m0 = blockIdx.x * 128;
    const int b  = blockIdx.y;

    const __nv_bfloat16* Bh = Bhi + (long)b * bBatchStride;
    const __nv_bfloat16* Bl = SPLIT ? (Blo + (long)b * (64L * NN)) : (const __nv_bfloat16*)nullptr;
    float* Cb = C + (long)b * cBatchStride;

    auto load_chunk = [&](int kc) {
        uint32_t st = sbase + (uint32_t)(kc % STAGES) * STAGE_BYTES;
        long gc = (long)kc * BK;
        // A hi: 1024 cp16 (128 rows x 8)
        #pragma unroll
        for (int p = 0; p < 4; p++) {
            int idx = tid + p * 256;
            int r = idx >> 3, c16 = idx & 7;
            cp16(st + OFF_A_T + swz(r, c16 * 16), Ahi + (long)(m0 + r) * NN + gc + c16 * 8);
        }
        if (SPLIT) {
            #pragma unroll
            for (int p = 0; p < 4; p++) {
                int idx = tid + p * 256;
                int r = idx >> 3, c16 = idx & 7;
                cp16(st + OFF_AL_T + swz(r, c16 * 16), Alo + (long)(m0 + r) * NN + gc + c16 * 8);
            }
        }
        // B hi: NB rows
        #pragma unroll
        for (int p = 0; p < NB / 32; p++) {
            int idx = tid + p * 256;
            int r = idx >> 3, c16 = idx & 7;
            cp16(st + OFF_B_T + swz(r, c16 * 16), Bh + (long)r * NN + gc + c16 * 8);
        }
        if (SPLIT) {
            #pragma unroll
            for (int p = 0; p < 2; p++) {
                int idx = tid + p * 256;
                int r = idx >> 3, c16 = idx & 7;
                cp16(st + OFF_BL_T + swz(r, c16 * 16), Bl + (long)r * NN + gc + c16 * 8);
            }
        }
        CP_COMMIT();
    };

    // ldmatrix address builders (row-major 128B rows, swizzled)
    auto lda_addr = [&](uint32_t base, int r0, int kb) -> uint32_t {
        int grp = lane >> 3;
        int row = r0 + (lane & 7) + ((grp & 1) << 3);
        int kb2 = kb + ((grp >> 1) << 4);
        return base + swz(row, kb2);
    };
    auto ldb_addr = [&](uint32_t base, int n0, int kb) -> uint32_t {
        int grp = lane >> 3;
        int row = n0 + (lane & 7) + ((grp >> 1) << 3);
        int kb2 = kb + ((grp & 1) << 4);
        return base + swz(row, kb2);
    };

    float acc[MT][NT][4] = {};

    load_chunk(0);
    load_chunk(1);

    for (int kc = 0; kc < NC; kc++) {
        if (kc + 2 < NC) load_chunk(kc + 2);
        if (kc + 2 < NC)      { CP_WAIT2(); }
        else if (kc + 1 < NC) { CP_WAIT1(); }
        else                  { CP_WAIT0(); }
        __syncthreads();

        uint32_t st = sbase + (uint32_t)(kc % STAGES) * STAGE_BYTES;
        #pragma unroll
        for (int ks = 0; ks < 4; ks++) {
            int kb = ks * 32;                       // 16 bf16 = 32 bytes per k-step
            uint32_t afh[MT][4];
            #pragma unroll
            for (int mt = 0; mt < MT; mt++)
                ldsm4(afh[mt], lda_addr(st + OFF_A_T, wm * MT * 16 + mt * 16, kb));
            uint32_t bfh[NT * 2];
            #pragma unroll
            for (int p = 0; p < NT / 2; p++)
                ldsm4(&bfh[p * 4], ldb_addr(st + OFF_B_T, wn * 64 + p * 16, kb));
            #pragma unroll
            for (int mt = 0; mt < MT; mt++)
                #pragma unroll
                for (int nt = 0; nt < NT; nt++)
                    mma_bf16(acc[mt][nt], afh[mt], &bfh[nt * 2]);
            if (SPLIT) {
                uint32_t afl[MT][4];
                #pragma unroll
                for (int mt = 0; mt < MT; mt++)
                    ldsm4(afl[mt], lda_addr(st + OFF_AL_T, wm * MT * 16 + mt * 16, kb));
                #pragma unroll
                for (int mt = 0; mt < MT; mt++)
                    #pragma unroll
                    for (int nt = 0; nt < NT; nt++)
                        mma_bf16(acc[mt][nt], afl[mt], &bfh[nt * 2]);
                if (wn == 0) {
                    uint32_t bfl[NT * 2];
                    #pragma unroll
                    for (int p = 0; p < NT / 2; p++)
                        ldsm4(&bfl[p * 4], ldb_addr(st + OFF_BL_T, p * 16, kb));
                    #pragma unroll
                    for (int mt = 0; mt < MT; mt++)
                        #pragma unroll
                        for (int nt = 0; nt < NT; nt++)
                            mma_bf16(acc[mt][nt], afh[mt], &bfl[nt * 2]);
                }
            }
        }
        __syncthreads();
    }

    // store C (fp32)
    #pragma unroll
    for (int mt = 0; mt < MT; mt++) {
        int r = m0 + wm * MT * 16 + mt * 16 + (lane >> 2);
        #pragma unroll
        for (int nt = 0; nt < NT; nt++) {
            int c = wn * 64 + nt * 8 + 2 * (lane & 3);
            *(float2*)(Cb + (long)r * NB + c)       = make_float2(acc[mt][nt][0], acc[mt][nt][1]);
            *(float2*)(Cb + (long)(r + 8) * NB + c) = make_float2(acc[mt][nt][2], acc[mt][nt][3]);
        }
    }
}

// ===========================================================================
// Small batched SGEMM (fp32 SIMT) for Dx / Dc (K=64)
// ===========================================================================
template<int BM, int BN, int BK, int TM, int TN>
__global__ void __launch_bounds__((BM / TM) * (BN / TN), 2)
sgemm_batched(const float* __restrict__ A, const float* __restrict__ Bm,
              float* __restrict__ C, int Kd, int lda, int ldb, int ldc,
              long aStride, int aDiv, long bStride, int bMod, long cStride)
{
    constexpr int THREADS = (BM / TM) * (BN / TN);
    constexpr int AF4 = BM * BK / 4;
    constexpr int BF4 = BK * BN / 4;
    constexpr int AP = (AF4 + THREADS - 1) / THREADS;
    constexpr int BP = (BF4 + THREADS - 1) / THREADS;

    const int z = blockIdx.z;
    const float* Ab = A + (long)(z / aDiv) * aStride;
    const float* Bb = Bm + (long)(z % bMod) * bStride;
    float* Cb = C + (long)z * cStride;

    const int m0 = blockIdx.y * BM;
    const int n0 = blockIdx.x * BN;

    __shared__ float As[BK][BM];
    __shared__ float Bs[BK][BN];

    const int tid = threadIdx.x;
    const int tx = tid % (BN / TN);
    const int ty = tid / (BN / TN);

    float acc[TM][TN] = {};
    float4 aReg[AP], bReg[BP];

    auto loadA = [&](int kt) {
        #pragma unroll
        for (int p = 0; p < AP; p++) {
            int idx = tid + p * THREADS;
            if (AF4 % THREADS == 0 || idx < AF4) {
                int r = idx / (BK / 4);
                int c = idx % (BK / 4);
                aReg[p] = *(const float4*)(Ab + (long)(m0 + r) * lda + kt + c * 4);
            }
        }
    };
    auto loadB = [&](int kt) {
        #pragma unroll
        for (int p = 0; p < BP; p++) {
            int idx = tid + p * THREADS;
            if (BF4 % THREADS == 0 || idx < BF4) {
                int r = idx / (BN / 4);
                int c = idx % (BN / 4);
                bReg[p] = *(const float4*)(Bb + (long)(kt + r) * ldb + n0 + c * 4);
            }
        }
    };
    auto storeA = [&]() {
        #pragma unroll
        for (int p = 0; p < AP; p++) {
            int idx = tid + p * THREADS;
            if (AF4 % THREADS == 0 || idx < AF4) {
                int r = idx / (BK / 4);
                int c = idx % (BK / 4);
                As[c * 4 + 0][r] = aReg[p].x;
                As[c * 4 + 1][r] = aReg[p].y;
                As[c * 4 + 2][r] = aReg[p].z;
                As[c * 4 + 3][r] = aReg[p].w;
            }
        }
    };
    auto storeB = [&]() {
        #pragma unroll
        for (int p = 0; p < BP; p++) {
            int idx = tid + p * THREADS;
            if (BF4 % THREADS == 0 || idx < BF4) {
                int r = idx / (BN / 4);
                int c = idx % (BN / 4);
                *(float4*)(&Bs[r][c * 4]) = bReg[p];
            }
        }
    };

    loadA(0); loadB(0);
    storeA(); storeB();
    __syncthreads();

    for (int kt = 0; kt < Kd; kt += BK) {
        bool more = (kt + BK) < Kd;
        if (more) { loadA(kt + BK); loadB(kt + BK); }
        #pragma unroll
        for (int kk = 0; kk < BK; kk++) {
            float af[TM], bf[TN];
            #pragma unroll
            for (int i = 0; i < TM; i++) af[i] = As[kk][ty * TM + i];
            #pragma unroll
            for (int j = 0; j < TN; j++) bf[j] = Bs[kk][tx * TN + j];
            #pragma unroll
            for (int i = 0; i < TM; i++)
                #pragma unroll
                for (int j = 0; j < TN; j++)
                    acc[i][j] = fmaf(af[i], bf[j], acc[i][j]);
        }
        __syncthreads();
        if (more) { storeA(); storeB(); __syncthreads(); }
    }

    #pragma unroll
    for (int i = 0; i < TM; i++) {
        float* cr = Cb + (long)(m0 + ty * TM + i) * ldc + n0 + tx * TN;
        #pragma unroll
        for (int j = 0; j < TN; j += 4) {
            *(float4*)(cr + j) = make_float4(acc[i][j], acc[i][j + 1],
                                             acc[i][j + 2], acc[i][j + 3]);
        }
    }
}

// ===========================================================================
// Epilogue: out[b,n,o] = sum_k gamma[b,n,k] * E[ReLU(N(cx0+Dx, Dc))]
// ===========================================================================
__global__ void __launch_bounds__(256) epilogue_kernel(float* __restrict__ out) {
    long idx = (long)blockIdx.x * 256 + threadIdx.x;
    long row = idx >> 6;
    int o = (int)(idx & 63);
    int b = (int)(row >> 12);
    int n = (int)(row & 4095);

    float cx0 = g_scratch[OFF_G1 + row * 128 + o];
    const float* gam = g_scratch + OFF_GAMMA + row * KK;

    float acc = 0.f;
    #pragma unroll
    for (int k = 0; k < KK; k++) {
        long zoff = ((long)(b * KK + k) << 18) + ((long)n << 6) + o;
        float mean = cx0 + g_scratch[OFF_DX + zoff];
        float var  = g_scratch[OFF_DC + zoff];
        float ex;
        float sd = sqrtf(fmaxf(var, 0.f));
        if (sd > 0.f) {
            float zz  = mean / sd;
            float pdf = expf(-0.5f * zz * zz) * 0.3989422804014327f;
            float cdf = 0.5f * (1.f + erff(zz * 0.7071067811865476f));
            ex = mean * cdf + sd * pdf;
        } else {
            ex = fmaxf(mean, 0.f);
        }
        acc = fmaf(gam[k], ex, acc);
    }
    out[idx] = acc;
}

// ===========================================================================
// Launch
// ===========================================================================
extern "C" void kernel_launch(void* const* d_in, const int* in_sizes, int n_in,
                              void* d_out, int out_size) {
    const float* shift = (const float*)d_in[0];
    const float* A2    = (const float*)d_in[1];
    const float* feat  = (const float*)d_in[2];
    const float* W     = (const float*)d_in[3];
    const float* pi    = (const float*)d_in[4];
    const float* mu    = (const float*)d_in[5];
    const float* sigma = (const float*)d_in[6];
    float* out = (float*)d_out;

    float* scr = nullptr;
    cudaGetSymbolAddress((void**)&scr, g_scratch);

    __nv_bfloat16* shift_hi = (__nv_bfloat16*)(scr + OFF_SHIFT_HI);
    __nv_bfloat16* shift_lo = (__nv_bfloat16*)(scr + OFF_SHIFT_LO);
    __nv_bfloat16* a2bf     = (__nv_bfloat16*)(scr + OFF_A2BF);
    __nv_bfloat16* c1thi    = (__nv_bfloat16*)(scr + OFF_C1THI);
    __nv_bfloat16* c1tlo    = (__nv_bfloat16*)(scr + OFF_C1TLO);

    // conversions
    const int n4 = NN * NN / 4;
    convert_split_kernel<<<(n4 + 255) / 256, 256>>>(
        (const float4*)shift, (uint2*)shift_hi, (uint2*)shift_lo, n4);
    convert_split_kernel<<<(n4 + 255) / 256, 256>>>(
        (const float4*)A2, (uint2*)a2bf, nullptr, n4);

    // prep
    prep_mv_kernel<<<(KK * 64 * 64 + 255) / 256, 256>>>(W, mu, sigma);
    prep_rows_kernel<<<BB * NN / 8, 256>>>(feat, W, mu, sigma, pi);
    transpose_c1_kernel<<<dim3(NN / 32, 4, BB), dim3(32, 32)>>>();

    // G1 = shift @ [tx0 | mask]  (split bf16, mma.sync)
    {
        constexpr int STAGE1 = 32768 + 128 * 128 + 8192;   // 57344
        constexpr int SMEM1 = 3 * STAGE1;                  // 172032
        cudaFuncSetAttribute(mma_gemm_kernel<128, true>,
                             cudaFuncAttributeMaxDynamicSharedMemorySize, SMEM1);
        mma_gemm_kernel<128, true><<<dim3(NN / 128, BB), 256, SMEM1>>>(
            shift_hi, shift_lo, c1thi, c1tlo, scr + OFF_G1,
            /*bBatchStride=*/128L * NN, /*cBatchStride=*/(long)NN * 128);
    }

    // G2 = A2 @ mask  (plain bf16, mma.sync); B = mask rows of C1Thi
    {
        constexpr int STAGE2 = 16384 + 64 * 128;           // 24576
        constexpr int SMEM2 = 3 * STAGE2;                  // 73728
        cudaFuncSetAttribute(mma_gemm_kernel<64, false>,
                             cudaFuncAttributeMaxDynamicSharedMemorySize, SMEM2);
        mma_gemm_kernel<64, false><<<dim3(NN / 128, BB), 256, SMEM2>>>(
            a2bf, nullptr, c1thi + 64L * NN, nullptr, scr + OFF_G2,
            /*bBatchStride=*/128L * NN, /*cBatchStride=*/(long)NN * 64);
    }

    // Dx[b,k] = S[b] @ M_k
    sgemm_batched<128, 64, 8, 8, 4><<<dim3(1, NN / 128, BB * KK), 256>>>(
        scr + OFF_G1 + 64, scr + OFF_M, scr + OFF_DX,
        64, 128, 64, 64,
        (long)NN * 128, KK, 4096L, KK,
        (long)NN * 64);

    // Dc[b,k] = T[b] @ V_k
    sgemm_batched<128, 64, 8, 8, 4><<<dim3(1, NN / 128, BB * KK), 256>>>(
        scr + OFF_G2, scr + OFF_V, scr + OFF_DC,
        64, 64, 64, 64,
        (long)NN * 64, KK, 4096L, KK,
        (long)NN * 64);

    // fused ex_relu + mixture epilogue
    epilogue_kernel<<<BB * NN * 64 / 256, 256>>>(out);
}

// round 6
// speedup vs baseline: 5.0967x; 1.7782x over previous
#include <cuda_runtime.h>
#include <cuda_fp16.h>
#include <cstdint>
#include <math.h>

// Problem constants
#define NN 4096
#define FF 64
#define OO 64
#define KK 5
#define BB 8

// ---------------------------------------------------------------------------
// Scratch layout (float offsets into g_scratch)
// ---------------------------------------------------------------------------
#define OFF_G1      0L          // [B][4096][128] fp32: cols 0..63 U=shift@featc, 64..127 S=shift@mask
#define OFF_G2      4194304L    // [B][4096][64]  fp32: T=A2@mask
#define OFF_GAMMA   6291456L    // [B][4096][5] fp32
#define OFF_MT      6455296L    // fp16 [5][64(o)][64(f)]: mu[k,f]*W[f,o]    (10240 float slots)
#define OFF_VT      6465536L    // fp16 [5][64(o)][64(f)]: exp(sig)*W^2      (10240)
#define OFF_WT      6475776L    // fp16 [64(o)][64(f)]: W[f,o]               (2048)
#define OFF_SHIFT_H 6477824L    // fp16 [4096][4096]                         (8388608)
#define OFF_A2_H    14866432L   // fp16 [4096][4096]                         (8388608)
#define OFF_C1T     23255040L   // fp16 [B][128][4096]                       (2097152)
#define SCRATCH_TOTAL 25352192L

__device__ float g_scratch[SCRATCH_TOTAL];

// ===========================================================================
// PTX helpers (baseline ISA: cp.async, ldmatrix, mma.sync)
// ===========================================================================
__device__ __forceinline__ uint32_t smem_to_u32(const void* p) {
    uint32_t a;
    asm("{ .reg .u64 t; cvta.to.shared.u64 t, %1; cvt.u32.u64 %0, t; }"
        : "=r"(a) : "l"(p));
    return a;
}

__device__ __forceinline__ void cp16(uint32_t dst, const void* src) {
    asm volatile("cp.async.cg.shared.global [%0], [%1], 16;"
                 :: "r"(dst), "l"(src) : "memory");
}
#define CP_COMMIT() asm volatile("cp.async.commit_group;" ::: "memory")
#define CP_WAIT2()  asm volatile("cp.async.wait_group 2;" ::: "memory")
#define CP_WAIT1()  asm volatile("cp.async.wait_group 1;" ::: "memory")
#define CP_WAIT0()  asm volatile("cp.async.wait_group 0;" ::: "memory")

__device__ __forceinline__ void ldsm4(uint32_t* f, uint32_t addr) {
    asm volatile("ldmatrix.sync.aligned.m8n8.x4.shared.b16 {%0,%1,%2,%3}, [%4];"
                 : "=r"(f[0]), "=r"(f[1]), "=r"(f[2]), "=r"(f[3]) : "r"(addr));
}

__device__ __forceinline__ void mma_fp16(float* c, const uint32_t* a, const uint32_t* b) {
    asm volatile(
        "mma.sync.aligned.m16n8k16.row.col.f32.f16.f16.f32 "
        "{%0,%1,%2,%3}, {%4,%5,%6,%7}, {%8,%9}, {%0,%1,%2,%3};"
        : "+f"(c[0]), "+f"(c[1]), "+f"(c[2]), "+f"(c[3])
        : "r"(a[0]), "r"(a[1]), "r"(a[2]), "r"(a[3]), "r"(b[0]), "r"(b[1]));
}

// SW128 swizzle for 128-byte rows
__device__ __forceinline__ uint32_t swz(int row, int kb) {
    return (uint32_t)(row * 128 + (kb ^ ((row & 7) << 4)));
}

// ldmatrix address builders (row-major 128B rows, swizzled)
__device__ __forceinline__ uint32_t lda_addr(uint32_t base, int lane, int r0, int kb) {
    int grp = lane >> 3;
    int row = r0 + (lane & 7) + ((grp & 1) << 3);
    int kb2 = kb + ((grp >> 1) << 4);
    return base + swz(row, kb2);
}
__device__ __forceinline__ uint32_t ldb_addr(uint32_t base, int lane, int n0, int kb) {
    int grp = lane >> 3;
    int row = n0 + (lane & 7) + ((grp >> 1) << 3);
    int kb2 = kb + ((grp & 1) << 4);
    return base + swz(row, kb2);
}

// ===========================================================================
// fp32 -> fp16 conversion
// ===========================================================================
__global__ void __launch_bounds__(256) convert_h_kernel(
    const float4* __restrict__ src, uint2* __restrict__ dst, int n4)
{
    int i = blockIdx.x * 256 + threadIdx.x;
    if (i >= n4) return;
    float4 v = src[i];
    __half2 h01 = __floats2half2_rn(v.x, v.y);
    __half2 h23 = __floats2half2_rn(v.z, v.w);
    uint2 o;
    o.x = *reinterpret_cast<uint32_t*>(&h01);
    o.y = *reinterpret_cast<uint32_t*>(&h23);
    dst[i] = o;
}

// ===========================================================================
// P0: Mt[k][o][f] = mu[k,f]*W[f,o], Vt[k][o][f] = exp(sig[k,f])*W[f,o]^2,
//     Wt[o][f] = W[f,o]   (all fp16, B-operand layout: row=o, col=f)
// ===========================================================================
__global__ void prep_mv_kernel(const float* __restrict__ W,
                               const float* __restrict__ mu,
                               const float* __restrict__ sigma) {
    int idx = blockIdx.x * 256 + threadIdx.x;
    if (idx >= KK * 64 * 64) return;
    int k = idx >> 12;
    int o = (idx >> 6) & 63;
    int f = idx & 63;
    float w = W[f * 64 + o];
    __half* mt = (__half*)(g_scratch + OFF_MT);
    __half* vt = (__half*)(g_scratch + OFF_VT);
    __half* wt = (__half*)(g_scratch + OFF_WT);
    mt[idx] = __float2half(mu[k * 64 + f] * w);
    vt[idx] = __float2half(expf(sigma[k * 64 + f]) * w * w);
    if (k == 0) wt[o * 64 + f] = __float2half(w);
}

// ===========================================================================
// P1: gamma only. One warp per (b,n) row.
// ===========================================================================
__global__ void __launch_bounds__(256) prep_gamma_kernel(
    const float* __restrict__ feat, const float* __restrict__ mu,
    const float* __restrict__ sigma, const float* __restrict__ pi)
{
    __shared__ float mus[KK * 64];
    __shared__ float ivs[KK * 64];
    __shared__ float pis[KK];

    int tid = threadIdx.x;
    for (int i = tid; i < KK * 64; i += 256) {
        mus[i] = mu[i];
        ivs[i] = expf(-sigma[i]);
    }
    if (tid < KK) pis[tid] = pi[tid];
    __syncthreads();

    int warp = tid >> 5, lane = tid & 31;
    long row = (long)blockIdx.x * 8 + warp;
    const float* fr = feat + row * 64;

    float v0 = fr[lane], v1 = fr[lane + 32];
    bool  nm0 = isnan(v0), nm1 = isnan(v1);
    float f0 = nm0 ? 0.f : v0;
    float f1 = nm1 ? 0.f : v1;

    float lg[KK];
    #pragma unroll
    for (int k = 0; k < KK; k++) {
        float p = 0.f;
        if (!nm0) { float d = f0 - mus[k * 64 + lane];      p = fmaf(d * d, ivs[k * 64 + lane], p); }
        if (!nm1) { float d = f1 - mus[k * 64 + lane + 32]; p = fmaf(d * d, ivs[k * 64 + lane + 32], p); }
        #pragma unroll
        for (int off = 16; off > 0; off >>= 1) p += __shfl_xor_sync(0xffffffffu, p, off);
        lg[k] = pis[k] - 0.5f * p;
    }
    float mx = lg[0];
    #pragma unroll
    for (int k = 1; k < KK; k++) mx = fmaxf(mx, lg[k]);
    float e[KK], den = 0.f;
    #pragma unroll
    for (int k = 0; k < KK; k++) { e[k] = expf(lg[k] - mx); den += e[k]; }
    if (lane == 0) {
        float inv = 1.f / den;
        #pragma unroll
        for (int k = 0; k < KK; k++) g_scratch[OFF_GAMMA + row * KK + k] = e[k] * inv;
    }
}

// ===========================================================================
// Transpose features -> C1T fp16 [b][128][4096]
//   row c<64: sanitized feature col c; row 64+c: NaN mask col c
// ===========================================================================
__global__ void __launch_bounds__(1024) trans_feat_kernel(const float* __restrict__ feat) {
    __shared__ float t[32][33];
    int b = blockIdx.z;
    int m0 = blockIdx.x * 32, c0 = blockIdx.y * 32;
    int tx = threadIdx.x, ty = threadIdx.y;
    t[ty][tx] = feat[((long)b * NN + m0 + ty) * 64 + c0 + tx];
    __syncthreads();
    float v = t[tx][ty];
    int c = c0 + ty, m = m0 + tx;
    bool nm = isnan(v);
    __half* d = (__half*)(g_scratch + OFF_C1T);
    d[((long)b * 128 + c) * NN + m]      = __float2half(nm ? 0.f : v);
    d[((long)b * 128 + 64 + c) * NN + m] = __float2half(nm ? 1.f : 0.f);
}

// ===========================================================================
// fp16 warp-MMA GEMM: C[b] rows [m0,m0+128) = A @ B^T
//   A: [4096][4096] fp16 row-major. B: [NB][4096] fp16 K-major rows.
// ===========================================================================
template<int NB>
__global__ void __launch_bounds__(256, 2)
mma_gemm_h(const __half* __restrict__ A, const __half* __restrict__ B,
           float* __restrict__ C, long bBatchStride, long cBatchStride)
{
    constexpr int BK = 64;
    constexpr int NC = NN / BK;
    constexpr int STAGES = 3;
    constexpr int OFF_B_T = 16384;
    constexpr int STAGE_BYTES = 16384 + NB * 128;
    constexpr int WARPS_M = (NB == 128) ? 4 : 8;
    constexpr int MT = 128 / (WARPS_M * 16);
    constexpr int NT = 8;

    extern __shared__ char smem[];
    uint32_t sbase = smem_to_u32(smem);
    const int tid = threadIdx.x, wid = tid >> 5, lane = tid & 31;
    const int wm = wid % WARPS_M, wn = wid / WARPS_M;
    const int m0 = blockIdx.x * 128;
    const int b  = blockIdx.y;

    const __half* Bb = B + (long)b * bBatchStride;
    float* Cb = C + (long)b * cBatchStride;

    auto load_chunk = [&](int kc) {
        uint32_t st = sbase + (uint32_t)(kc % STAGES) * STAGE_BYTES;
        long gc = (long)kc * BK;
        #pragma unroll
        for (int p = 0; p < 4; p++) {
            int idx = tid + p * 256;
            int r = idx >> 3, c16 = idx & 7;
            cp16(st + swz(r, c16 * 16), A + (long)(m0 + r) * NN + gc + c16 * 8);
        }
        #pragma unroll
        for (int p = 0; p < NB / 32; p++) {
            int idx = tid + p * 256;
            int r = idx >> 3, c16 = idx & 7;
            cp16(st + OFF_B_T + swz(r, c16 * 16), Bb + (long)r * NN + gc + c16 * 8);
        }
        CP_COMMIT();
    };

    float acc[MT][NT][4] = {};

    load_chunk(0);
    load_chunk(1);

    for (int kc = 0; kc < NC; kc++) {
        if (kc + 2 < NC) load_chunk(kc + 2);
        if (kc + 2 < NC)      { CP_WAIT2(); }
        else if (kc + 1 < NC) { CP_WAIT1(); }
        else                  { CP_WAIT0(); }
        __syncthreads();

        uint32_t st = sbase + (uint32_t)(kc % STAGES) * STAGE_BYTES;
        #pragma unroll
        for (int ks = 0; ks < 4; ks++) {
            int kb = ks * 32;
            uint32_t af[MT][4];
            #pragma unroll
            for (int mt = 0; mt < MT; mt++)
                ldsm4(af[mt], lda_addr(st, lane, wm * MT * 16 + mt * 16, kb));
            uint32_t bf[NT * 2];
            #pragma unroll
            for (int p = 0; p < NT / 2; p++)
                ldsm4(&bf[p * 4], ldb_addr(st + OFF_B_T, lane, wn * 64 + p * 16, kb));
            #pragma unroll
            for (int mt = 0; mt < MT; mt++)
                #pragma unroll
                for (int nt = 0; nt < NT; nt++)
                    mma_fp16(acc[mt][nt], af[mt], &bf[nt * 2]);
        }
        __syncthreads();
    }

    #pragma unroll
    for (int mt = 0; mt < MT; mt++) {
        int r = m0 + wm * MT * 16 + mt * 16 + (lane >> 2);
        #pragma unroll
        for (int nt = 0; nt < NT; nt++) {
            int c = wn * 64 + nt * 8 + 2 * (lane & 3);
            *(float2*)(Cb + (long)r * NB + c)       = make_float2(acc[mt][nt][0], acc[mt][nt][1]);
            *(float2*)(Cb + (long)(r + 8) * NB + c) = make_float2(acc[mt][nt][2], acc[mt][nt][3]);
        }
    }
}

// ===========================================================================
// Fused tail: per 128-row tile of batch b:
//   ux = U @ W ; per k: dx = S@M_k, dc = T@V_k (fp16 mma, K=64)
//   out = sum_k gamma_k * ex_relu(ux+dx, dc)
// ===========================================================================
#define SM_S   0
#define SM_U   16384
#define SM_T   32768
#define SM_MT  49152
#define SM_VT  90112
#define SM_WT  131072
#define SM_G   139264
#define SM_TOT 141824

__global__ void __launch_bounds__(256) fused_tail_kernel(float* __restrict__ out) {
    extern __shared__ char smem[];
    uint32_t sbase = smem_to_u32(smem);
    const int tid = threadIdx.x, wid = tid >> 5, lane = tid & 31;
    const int wm = wid & 3, wn = wid >> 2;     // 4 x 2 warps: 32 rows x 32 cols each
    const int m0 = blockIdx.x * 128;
    const int b  = blockIdx.y;

    // Load Mt / Vt / Wt via cp.async with swizzled dst
    {
        const __half* mtg = (const __half*)(g_scratch + OFF_MT);
        const __half* vtg = (const __half*)(g_scratch + OFF_VT);
        const __half* wtg = (const __half*)(g_scratch + OFF_WT);
        for (int i = tid; i < 2560; i += 256) {      // 5*64*8 16B chunks
            int k = i >> 9, rem = i & 511;
            int o = rem >> 3, f16 = rem & 7;
            cp16(sbase + SM_MT + k * 8192 + swz(o, f16 * 16), mtg + (long)i * 8);
            cp16(sbase + SM_VT + k * 8192 + swz(o, f16 * 16), vtg + (long)i * 8);
        }
        for (int i = tid; i < 512; i += 256) {       // 64*8 chunks
            int o = i >> 3, f16 = i & 7;
            cp16(sbase + SM_WT + swz(o, f16 * 16), wtg + (long)i * 8);
        }
        CP_COMMIT();
    }

    // Convert U/S/T tiles fp32 -> fp16 into swizzled smem
    {
        const float* g1 = g_scratch + OFF_G1 + ((long)b * NN + m0) * 128;
        const float* g2 = g_scratch + OFF_G2 + ((long)b * NN + m0) * 64;
        for (int i = tid; i < 128 * 16; i += 256) {
            int r = i >> 4, f4 = i & 15;
            uint32_t off = (uint32_t)(r * 128 + ((f4 * 8) ^ ((r & 7) << 4)));
            float4 u = *(const float4*)(g1 + (long)r * 128 + f4 * 4);
            float4 s = *(const float4*)(g1 + (long)r * 128 + 64 + f4 * 4);
            float4 t = *(const float4*)(g2 + (long)r * 64 + f4 * 4);
            __half2 a0 = __floats2half2_rn(u.x, u.y), a1 = __floats2half2_rn(u.z, u.w);
            __half2 b0 = __floats2half2_rn(s.x, s.y), b1 = __floats2half2_rn(s.z, s.w);
            __half2 c0 = __floats2half2_rn(t.x, t.y), c1 = __floats2half2_rn(t.z, t.w);
            uint2 uv, sv, tv;
            uv.x = *reinterpret_cast<uint32_t*>(&a0); uv.y = *reinterpret_cast<uint32_t*>(&a1);
            sv.x = *reinterpret_cast<uint32_t*>(&b0); sv.y = *reinterpret_cast<uint32_t*>(&b1);
            tv.x = *reinterpret_cast<uint32_t*>(&c0); tv.y = *reinterpret_cast<uint32_t*>(&c1);
            *(uint2*)(smem + SM_U + off) = uv;
            *(uint2*)(smem + SM_S + off) = sv;
            *(uint2*)(smem + SM_T + off) = tv;
        }
        const float* gg = g_scratch + OFF_GAMMA + ((long)b * NN + m0) * KK;
        for (int i = tid; i < 128 * KK; i += 256)
            *(float*)(smem + SM_G + i * 4) = gg[i];
    }
    CP_WAIT0();
    __syncthreads();

    // ux = U @ W
    float ux[2][4][4] = {};
    #pragma unroll
    for (int ks = 0; ks < 4; ks++) {
        int kb = ks * 32;
        uint32_t af[2][4];
        #pragma unroll
        for (int mt = 0; mt < 2; mt++)
            ldsm4(af[mt], lda_addr(sbase + SM_U, lane, wm * 32 + mt * 16, kb));
        uint32_t bf[8];
        #pragma unroll
        for (int p = 0; p < 2; p++)
            ldsm4(&bf[p * 4], ldb_addr(sbase + SM_WT, lane, wn * 32 + p * 16, kb));
        #pragma unroll
        for (int mt = 0; mt < 2; mt++)
            #pragma unroll
            for (int nt = 0; nt < 4; nt++)
                mma_fp16(ux[mt][nt], af[mt], &bf[nt * 2]);
    }

    float oacc[2][4][4] = {};
    const float* sg = (const float*)(smem + SM_G);

    #pragma unroll 1
    for (int k = 0; k < KK; k++) {
        float dx[2][4][4] = {};
        float dc[2][4][4] = {};
        #pragma unroll
        for (int ks = 0; ks < 4; ks++) {
            int kb = ks * 32;
            uint32_t as[2][4], at[2][4];
            #pragma unroll
            for (int mt = 0; mt < 2; mt++) {
                ldsm4(as[mt], lda_addr(sbase + SM_S, lane, wm * 32 + mt * 16, kb));
                ldsm4(at[mt], lda_addr(sbase + SM_T, lane, wm * 32 + mt * 16, kb));
            }
            uint32_t bm[8], bv[8];
            #pragma unroll
            for (int p = 0; p < 2; p++) {
                ldsm4(&bm[p * 4], ldb_addr(sbase + SM_MT + k * 8192, lane, wn * 32 + p * 16, kb));
                ldsm4(&bv[p * 4], ldb_addr(sbase + SM_VT + k * 8192, lane, wn * 32 + p * 16, kb));
            }
            #pragma unroll
            for (int mt = 0; mt < 2; mt++)
                #pragma unroll
                for (int nt = 0; nt < 4; nt++) {
                    mma_fp16(dx[mt][nt], as[mt], &bm[nt * 2]);
                    mma_fp16(dc[mt][nt], at[mt], &bv[nt * 2]);
                }
        }
        // epilogue for component k
        #pragma unroll
        for (int mt = 0; mt < 2; mt++) {
            int rl0 = wm * 32 + mt * 16 + (lane >> 2);
            float g0 = sg[rl0 * KK + k];
            float g1v = sg[(rl0 + 8) * KK + k];
            #pragma unroll
            for (int nt = 0; nt < 4; nt++) {
                #pragma unroll
                for (int v = 0; v < 4; v++) {
                    float mean = ux[mt][nt][v] + dx[mt][nt][v];
                    float var  = dc[mt][nt][v];
                    float sd = sqrtf(fmaxf(var, 0.f));
                    float ex;
                    if (sd > 0.f) {
                        float zz = mean / sd;
                        ex = mean * normcdff(zz)
                           + sd * expf(-0.5f * zz * zz) * 0.3989422804014327f;
                    } else {
                        ex = fmaxf(mean, 0.f);
                    }
                    float g = (v < 2) ? g0 : g1v;
                    oacc[mt][nt][v] = fmaf(g, ex, oacc[mt][nt][v]);
                }
            }
        }
    }

    // store
    float* ob = out + ((long)b * NN + m0) * 64;
    #pragma unroll
    for (int mt = 0; mt < 2; mt++) {
        int r = wm * 32 + mt * 16 + (lane >> 2);
        #pragma unroll
        for (int nt = 0; nt < 4; nt++) {
            int c = wn * 32 + nt * 8 + 2 * (lane & 3);
            *(float2*)(ob + (long)r * 64 + c)       = make_float2(oacc[mt][nt][0], oacc[mt][nt][1]);
            *(float2*)(ob + (long)(r + 8) * 64 + c) = make_float2(oacc[mt][nt][2], oacc[mt][nt][3]);
        }
    }
}

// ===========================================================================
// Launch
// ===========================================================================
extern "C" void kernel_launch(void* const* d_in, const int* in_sizes, int n_in,
                              void* d_out, int out_size) {
    const float* shift = (const float*)d_in[0];
    const float* A2    = (const float*)d_in[1];
    const float* feat  = (const float*)d_in[2];
    const float* W     = (const float*)d_in[3];
    const float* pi    = (const float*)d_in[4];
    const float* mu    = (const float*)d_in[5];
    const float* sigma = (const float*)d_in[6];
    float* out = (float*)d_out;

    float* scr = nullptr;
    cudaGetSymbolAddress((void**)&scr, g_scratch);

    __half* shift_h = (__half*)(scr + OFF_SHIFT_H);
    __half* a2_h    = (__half*)(scr + OFF_A2_H);
    __half* c1t     = (__half*)(scr + OFF_C1T);

    // conversions
    const int n4 = NN * NN / 4;
    convert_h_kernel<<<(n4 + 255) / 256, 256>>>((const float4*)shift, (uint2*)shift_h, n4);
    convert_h_kernel<<<(n4 + 255) / 256, 256>>>((const float4*)A2, (uint2*)a2_h, n4);

    // prep
    prep_mv_kernel<<<(KK * 64 * 64 + 255) / 256, 256>>>(W, mu, sigma);
    prep_gamma_kernel<<<BB * NN / 8, 256>>>(feat, mu, sigma, pi);
    trans_feat_kernel<<<dim3(NN / 32, 2, BB), dim3(32, 32)>>>(feat);

    // G1 = shift @ [featc | mask]^T  (fp16 mma) -> U | S
    {
        constexpr int SMEM1 = 3 * (16384 + 128 * 128);   // 98304
        cudaFuncSetAttribute(mma_gemm_h<128>,
                             cudaFuncAttributeMaxDynamicSharedMemorySize, SMEM1);
        mma_gemm_h<128><<<dim3(NN / 128, BB), 256, SMEM1>>>(
            shift_h, c1t, scr + OFF_G1,
            /*bBatchStride=*/128L * NN, /*cBatchStride=*/(long)NN * 128);
    }

    // G2 = A2 @ mask^T  (fp16 mma) -> T
    {
        constexpr int SMEM2 = 3 * (16384 + 64 * 128);    // 73728
        cudaFuncSetAttribute(mma_gemm_h<64>,
                             cudaFuncAttributeMaxDynamicSharedMemorySize, SMEM2);
        mma_gemm_h<64><<<dim3(NN / 128, BB), 256, SMEM2>>>(
            a2_h, c1t + 64L * NN, scr + OFF_G2,
            /*bBatchStride=*/128L * NN, /*cBatchStride=*/(long)NN * 64);
    }

    // fused Dx/Dc + ex_relu + mixture
    {
        cudaFuncSetAttribute(fused_tail_kernel,
                             cudaFuncAttributeMaxDynamicSharedMemorySize, SM_TOT);
        fused_tail_kernel<<<dim3(NN / 128, BB), 256, SM_TOT>>>(out);
    }
}

// round 8
// speedup vs baseline: 5.2867x; 1.0373x over previous
#include <cuda_runtime.h>
#include <cuda_fp16.h>
#include <cstdint>
#include <math.h>

// Problem constants
#define NN 4096
#define FF 64
#define OO 64
#define KK 5
#define BB 8

// ---------------------------------------------------------------------------
// Scratch layout (float offsets into g_scratch)
// ---------------------------------------------------------------------------
#define OFF_GAMMA   0L          // [B][4096][5] fp32
#define OFF_MT      163840L     // fp16 [5][64(o)][64(f)]  (10240 float slots)
#define OFF_VT      174080L     // fp16 [5][64(o)][64(f)]  (10240)
#define OFF_WT      184320L     // fp16 [64(o)][64(f)]     (2048)
#define OFF_SHIFT_H 186368L     // fp16 [4096][4096]       (8388608)
#define OFF_A2_H    8574976L    // fp16 [4096][4096]       (8388608)
#define OFF_C1T     16963584L   // fp16 [B][128][4096]     (2097152)
#define SCRATCH_TOTAL 19060736L

__device__ float g_scratch[SCRATCH_TOTAL];

// ===========================================================================
// PTX helpers (baseline ISA: cp.async, ldmatrix, mma.sync)
// ===========================================================================
__device__ __forceinline__ uint32_t smem_to_u32(const void* p) {
    uint32_t a;
    asm("{ .reg .u64 t; cvta.to.shared.u64 t, %1; cvt.u32.u64 %0, t; }"
        : "=r"(a) : "l"(p));
    return a;
}

__device__ __forceinline__ void cp16(uint32_t dst, const void* src) {
    asm volatile("cp.async.cg.shared.global [%0], [%1], 16;"
                 :: "r"(dst), "l"(src) : "memory");
}
#define CP_COMMIT() asm volatile("cp.async.commit_group;" ::: "memory")
#define CP_WAIT2()  asm volatile("cp.async.wait_group 2;" ::: "memory")
#define CP_WAIT1()  asm volatile("cp.async.wait_group 1;" ::: "memory")
#define CP_WAIT0()  asm volatile("cp.async.wait_group 0;" ::: "memory")

__device__ __forceinline__ void ldsm4(uint32_t* f, uint32_t addr) {
    asm volatile("ldmatrix.sync.aligned.m8n8.x4.shared.b16 {%0,%1,%2,%3}, [%4];"
                 : "=r"(f[0]), "=r"(f[1]), "=r"(f[2]), "=r"(f[3]) : "r"(addr));
}

__device__ __forceinline__ void mma_fp16(float* c, const uint32_t* a, const uint32_t* b) {
    asm volatile(
        "mma.sync.aligned.m16n8k16.row.col.f32.f16.f16.f32 "
        "{%0,%1,%2,%3}, {%4,%5,%6,%7}, {%8,%9}, {%0,%1,%2,%3};"
        : "+f"(c[0]), "+f"(c[1]), "+f"(c[2]), "+f"(c[3])
        : "r"(a[0]), "r"(a[1]), "r"(a[2]), "r"(a[3]), "r"(b[0]), "r"(b[1]));
}

// SW128 swizzle for 128-byte rows
__device__ __forceinline__ uint32_t swz(int row, int kb) {
    return (uint32_t)(row * 128 + (kb ^ ((row & 7) << 4)));
}

__device__ __forceinline__ uint32_t lda_addr(uint32_t base, int lane, int r0, int kb) {
    int grp = lane >> 3;
    int row = r0 + (lane & 7) + ((grp & 1) << 3);
    int kb2 = kb + ((grp >> 1) << 4);
    return base + swz(row, kb2);
}
__device__ __forceinline__ uint32_t ldb_addr(uint32_t base, int lane, int n0, int kb) {
    int grp = lane >> 3;
    int row = n0 + (lane & 7) + ((grp >> 1) << 3);
    int kb2 = kb + ((grp & 1) << 4);
    return base + swz(row, kb2);
}

// ===========================================================================
// fp32 -> fp16 conversion (both big matrices in one launch; y selects matrix)
// ===========================================================================
__global__ void __launch_bounds__(256) convert_h_kernel(
    const float4* __restrict__ s0, uint2* __restrict__ d0,
    const float4* __restrict__ s1, uint2* __restrict__ d1, int n4)
{
    int i = blockIdx.x * 256 + threadIdx.x;
    if (i >= n4) return;
    const float4* src = blockIdx.y ? s1 : s0;
    uint2* dst = blockIdx.y ? d1 : d0;
    float4 v = src[i];
    __half2 h01 = __floats2half2_rn(v.x, v.y);
    __half2 h23 = __floats2half2_rn(v.z, v.w);
    uint2 o;
    o.x = *reinterpret_cast<uint32_t*>(&h01);
    o.y = *reinterpret_cast<uint32_t*>(&h23);
    dst[i] = o;
}

// ===========================================================================
// P0: Mt[k][o][f] = mu[k,f]*W[f,o], Vt[k][o][f] = exp(sig[k,f])*W[f,o]^2,
//     Wt[o][f] = W[f,o]   (fp16, B-operand layout)
// ===========================================================================
__global__ void prep_mv_kernel(const float* __restrict__ W,
                               const float* __restrict__ mu,
                               const float* __restrict__ sigma) {
    int idx = blockIdx.x * 256 + threadIdx.x;
    if (idx >= KK * 64 * 64) return;
    int k = idx >> 12;
    int o = (idx >> 6) & 63;
    int f = idx & 63;
    float w = W[f * 64 + o];
    __half* mt = (__half*)(g_scratch + OFF_MT);
    __half* vt = (__half*)(g_scratch + OFF_VT);
    __half* wt = (__half*)(g_scratch + OFF_WT);
    mt[idx] = __float2half(mu[k * 64 + f] * w);
    vt[idx] = __float2half(expf(sigma[k * 64 + f]) * w * w);
    if (k == 0) wt[o * 64 + f] = __float2half(w);
}

// ===========================================================================
// P1: gamma. One warp per (b,n) row.
// ===========================================================================
__global__ void __launch_bounds__(256) prep_gamma_kernel(
    const float* __restrict__ feat, const float* __restrict__ mu,
    const float* __restrict__ sigma, const float* __restrict__ pi)
{
    __shared__ float mus[KK * 64];
    __shared__ float ivs[KK * 64];
    __shared__ float pis[KK];

    int tid = threadIdx.x;
    for (int i = tid; i < KK * 64; i += 256) {
        mus[i] = mu[i];
        ivs[i] = expf(-sigma[i]);
    }
    if (tid < KK) pis[tid] = pi[tid];
    __syncthreads();

    int warp = tid >> 5, lane = tid & 31;
    long row = (long)blockIdx.x * 8 + warp;
    const float* fr = feat + row * 64;

    float v0 = fr[lane], v1 = fr[lane + 32];
    bool  nm0 = isnan(v0), nm1 = isnan(v1);
    float f0 = nm0 ? 0.f : v0;
    float f1 = nm1 ? 0.f : v1;

    float lg[KK];
    #pragma unroll
    for (int k = 0; k < KK; k++) {
        float p = 0.f;
        if (!nm0) { float d = f0 - mus[k * 64 + lane];      p = fmaf(d * d, ivs[k * 64 + lane], p); }
        if (!nm1) { float d = f1 - mus[k * 64 + lane + 32]; p = fmaf(d * d, ivs[k * 64 + lane + 32], p); }
        #pragma unroll
        for (int off = 16; off > 0; off >>= 1) p += __shfl_xor_sync(0xffffffffu, p, off);
        lg[k] = pis[k] - 0.5f * p;
    }
    float mx = lg[0];
    #pragma unroll
    for (int k = 1; k < KK; k++) mx = fmaxf(mx, lg[k]);
    float e[KK], den = 0.f;
    #pragma unroll
    for (int k = 0; k < KK; k++) { e[k] = expf(lg[k] - mx); den += e[k]; }
    if (lane == 0) {
        float inv = 1.f / den;
        #pragma unroll
        for (int k = 0; k < KK; k++) g_scratch[OFF_GAMMA + row * KK + k] = e[k] * inv;
    }
}

// ===========================================================================
// Transpose features -> C1T fp16 [b][128][4096]
// ===========================================================================
__global__ void __launch_bounds__(1024) trans_feat_kernel(const float* __restrict__ feat) {
    __shared__ float t[32][33];
    int b = blockIdx.z;
    int m0 = blockIdx.x * 32, c0 = blockIdx.y * 32;
    int tx = threadIdx.x, ty = threadIdx.y;
    t[ty][tx] = feat[((long)b * NN + m0 + ty) * 64 + c0 + tx];
    __syncthreads();
    float v = t[tx][ty];
    int c = c0 + ty, m = m0 + tx;
    bool nm = isnan(v);
    __half* d = (__half*)(g_scratch + OFF_C1T);
    d[((long)b * 128 + c) * NN + m]      = __float2half(nm ? 0.f : v);
    d[((long)b * 128 + 64 + c) * NN + m] = __float2half(nm ? 1.f : 0.f);
}

// ===========================================================================
// MEGA kernel: per (128-row tile, b):
//   mainloop: U|S = shift @ c1t^T (N=128), T = A2 @ mask^T (N=64), fp16 mma
//   tail: ux = U@W; per k: dx=S@M_k, dc=T@V_k; out = sum_k gamma*ex_relu
// ===========================================================================
#define STG_BYTES 49152          // per-stage: shift 16K | A2 16K | B 16K
#define OFF_AS 0
#define OFF_AA 16384
#define OFF_B  32768
// tail layout (reuses stage area)
#define SM_S   0
#define SM_U   16384
#define SM_T   32768
#define SM_MT  49152
#define SM_VT  90112
#define SM_WT  131072
#define SM_G   139264
#define SM_TOT (3 * STG_BYTES)   // 147456

__global__ void __launch_bounds__(256, 1)
mega_kernel(const __half* __restrict__ Ash, const __half* __restrict__ Aa2,
            const __half* __restrict__ C1T, float* __restrict__ out)
{
    constexpr int BK = 64;
    constexpr int NC = NN / BK;

    extern __shared__ char smem[];
    uint32_t sbase = smem_to_u32(smem);
    const int tid = threadIdx.x, wid = tid >> 5, lane = tid & 31;
    const int wmA = wid & 3, wnA = wid >> 2;   // U|S: 4x2 warps (32 rows x 64 cols)
    const int m0 = blockIdx.x * 128;
    const int b  = blockIdx.y;

    const __half* Bb = C1T + (long)b * (128L * NN);

    auto load_chunk = [&](int kc) {
        uint32_t st = sbase + (uint32_t)(kc % 3) * STG_BYTES;
        long gc = (long)kc * BK;
        #pragma unroll
        for (int p = 0; p < 4; p++) {
            int idx = tid + p * 256;
            int r = idx >> 3, c16 = idx & 7;
            cp16(st + OFF_AS + swz(r, c16 * 16), Ash + (long)(m0 + r) * NN + gc + c16 * 8);
            cp16(st + OFF_AA + swz(r, c16 * 16), Aa2 + (long)(m0 + r) * NN + gc + c16 * 8);
            cp16(st + OFF_B  + swz(r, c16 * 16), Bb  + (long)r * NN + gc + c16 * 8);
        }
        CP_COMMIT();
    };

    float accUS[2][8][4] = {};
    float accT[8][4] = {};

    load_chunk(0);
    load_chunk(1);

    for (int kc = 0; kc < NC; kc++) {
        if (kc + 2 < NC) load_chunk(kc + 2);
        if (kc + 2 < NC)      { CP_WAIT2(); }
        else if (kc + 1 < NC) { CP_WAIT1(); }
        else                  { CP_WAIT0(); }
        __syncthreads();

        uint32_t st = sbase + (uint32_t)(kc % 3) * STG_BYTES;
        #pragma unroll
        for (int ks = 0; ks < 4; ks++) {
            int kb = ks * 32;
            // U|S part
            uint32_t afS[2][4];
            #pragma unroll
            for (int mt = 0; mt < 2; mt++)
                ldsm4(afS[mt], lda_addr(st + OFF_AS, lane, wmA * 32 + mt * 16, kb));
            uint32_t bf[16];
            #pragma unroll
            for (int p = 0; p < 4; p++)
                ldsm4(&bf[p * 4], ldb_addr(st + OFF_B, lane, wnA * 64 + p * 16, kb));
            #pragma unroll
            for (int mt = 0; mt < 2; mt++)
                #pragma unroll
                for (int nt = 0; nt < 8; nt++)
                    mma_fp16(accUS[mt][nt], afS[mt], &bf[nt * 2]);
            // T part (A2 rows wid*16, B = mask rows 64..127)
            uint32_t afA[4];
            ldsm4(afA, lda_addr(st + OFF_AA, lane, wid * 16, kb));
            uint32_t bm[16];
            #pragma unroll
            for (int p = 0; p < 4; p++)
                ldsm4(&bm[p * 4], ldb_addr(st + OFF_B, lane, 64 + p * 16, kb));
            #pragma unroll
            for (int nt = 0; nt < 8; nt++)
                mma_fp16(accT[nt], afA, &bm[nt * 2]);
        }
        __syncthreads();
    }

    // --------------------------------------------------------------
    // Spill fragments to SMEM as fp16; fetch Mt/Vt/Wt/gamma
    // --------------------------------------------------------------
    __syncthreads();   // all warps done reading stage smem

    // cp.async constants into SM_MT / SM_VT / SM_WT / SM_G (bytes >= 49152)
    {
        const __half* mtg = (const __half*)(g_scratch + OFF_MT);
        const __half* vtg = (const __half*)(g_scratch + OFF_VT);
        const __half* wtg = (const __half*)(g_scratch + OFF_WT);
        for (int i = tid; i < 2560; i += 256) {
            int k = i >> 9, rem = i & 511;
            int o = rem >> 3, f16 = rem & 7;
            cp16(sbase + SM_MT + k * 8192 + swz(o, f16 * 16), mtg + (long)i * 8);
            cp16(sbase + SM_VT + k * 8192 + swz(o, f16 * 16), vtg + (long)i * 8);
        }
        for (int i = tid; i < 512; i += 256) {
            int o = i >> 3, f16 = i & 7;
            cp16(sbase + SM_WT + swz(o, f16 * 16), wtg + (long)i * 8);
        }
        const char* gg = (const char*)(g_scratch + OFF_GAMMA + ((long)b * NN + m0) * KK);
        if (tid < 160) cp16(sbase + SM_G + tid * 16, gg + tid * 16);
        CP_COMMIT();
    }

    // fragment -> SMEM fp16 stores (bytes 0..49151 = stage 0 area)
    {
        int rl = lane >> 2;
        int cl = 2 * (lane & 3);
        #pragma unroll
        for (int mt = 0; mt < 2; mt++) {
            int r0 = wmA * 32 + mt * 16 + rl;
            #pragma unroll
            for (int nt = 0; nt < 8; nt++) {
                int c = wnA * 64 + nt * 8 + cl;
                int f = c & 63;
                uint32_t base = (wnA == 0) ? (sbase + SM_U) : (sbase + SM_S);
                __half2 lo = __floats2half2_rn(accUS[mt][nt][0], accUS[mt][nt][1]);
                __half2 hi = __floats2half2_rn(accUS[mt][nt][2], accUS[mt][nt][3]);
                *(uint32_t*)(smem + (base - sbase) + r0 * 128 + ((f * 2) ^ ((r0 & 7) << 4))) =
                    *reinterpret_cast<uint32_t*>(&lo);
                int r1 = r0 + 8;
                *(uint32_t*)(smem + (base - sbase) + r1 * 128 + ((f * 2) ^ ((r1 & 7) << 4))) =
                    *reinterpret_cast<uint32_t*>(&hi);
            }
        }
        int r0 = wid * 16 + rl;
        #pragma unroll
        for (int nt = 0; nt < 8; nt++) {
            int f = nt * 8 + cl;
            __half2 lo = __floats2half2_rn(accT[nt][0], accT[nt][1]);
            __half2 hi = __floats2half2_rn(accT[nt][2], accT[nt][3]);
            *(uint32_t*)(smem + SM_T + r0 * 128 + ((f * 2) ^ ((r0 & 7) << 4))) =
                *reinterpret_cast<uint32_t*>(&lo);
            int r1 = r0 + 8;
            *(uint32_t*)(smem + SM_T + r1 * 128 + ((f * 2) ^ ((r1 & 7) << 4))) =
                *reinterpret_cast<uint32_t*>(&hi);
        }
    }
    CP_WAIT0();
    __syncthreads();

    // --------------------------------------------------------------
    // Tail: ux = U @ W ; per k: dx = S@M_k, dc = T@V_k ; mixture epilogue
    // --------------------------------------------------------------
    const int wm = wid & 3, wn = wid >> 2;

    float ux[2][4][4] = {};
    #pragma unroll
    for (int ks = 0; ks < 4; ks++) {
        int kb = ks * 32;
        uint32_t af[2][4];
        #pragma unroll
        for (int mt = 0; mt < 2; mt++)
            ldsm4(af[mt], lda_addr(sbase + SM_U, lane, wm * 32 + mt * 16, kb));
        uint32_t bf[8];
        #pragma unroll
        for (int p = 0; p < 2; p++)
            ldsm4(&bf[p * 4], ldb_addr(sbase + SM_WT, lane, wn * 32 + p * 16, kb));
        #pragma unroll
        for (int mt = 0; mt < 2; mt++)
            #pragma unroll
            for (int nt = 0; nt < 4; nt++)
                mma_fp16(ux[mt][nt], af[mt], &bf[nt * 2]);
    }

    float oacc[2][4][4] = {};
    const float* sg = (const float*)(smem + SM_G);

    #pragma unroll 1
    for (int k = 0; k < KK; k++) {
        float dx[2][4][4] = {};
        float dc[2][4][4] = {};
        #pragma unroll
        for (int ks = 0; ks < 4; ks++) {
            int kb = ks * 32;
            uint32_t as[2][4], at[2][4];
            #pragma unroll
            for (int mt = 0; mt < 2; mt++) {
                ldsm4(as[mt], lda_addr(sbase + SM_S, lane, wm * 32 + mt * 16, kb));
                ldsm4(at[mt], lda_addr(sbase + SM_T, lane, wm * 32 + mt * 16, kb));
            }
            uint32_t bm[8], bv[8];
            #pragma unroll
            for (int p = 0; p < 2; p++) {
                ldsm4(&bm[p * 4], ldb_addr(sbase + SM_MT + k * 8192, lane, wn * 32 + p * 16, kb));
                ldsm4(&bv[p * 4], ldb_addr(sbase + SM_VT + k * 8192, lane, wn * 32 + p * 16, kb));
            }
            #pragma unroll
            for (int mt = 0; mt < 2; mt++)
                #pragma unroll
                for (int nt = 0; nt < 4; nt++) {
                    mma_fp16(dx[mt][nt], as[mt], &bm[nt * 2]);
                    mma_fp16(dc[mt][nt], at[mt], &bv[nt * 2]);
                }
        }
        #pragma unroll
        for (int mt = 0; mt < 2; mt++) {
            int rl0 = wm * 32 + mt * 16 + (lane >> 2);
            float g0 = sg[rl0 * KK + k];
            float g1v = sg[(rl0 + 8) * KK + k];
            #pragma unroll
            for (int nt = 0; nt < 4; nt++) {
                #pragma unroll
                for (int v = 0; v < 4; v++) {
                    float mean = ux[mt][nt][v] + dx[mt][nt][v];
                    float var  = dc[mt][nt][v];
                    float sd = sqrtf(fmaxf(var, 0.f));
                    float ex;
                    if (sd > 0.f) {
                        float zz = mean / sd;
                        ex = mean * normcdff(zz)
                           + sd * expf(-0.5f * zz * zz) * 0.3989422804014327f;
                    } else {
                        ex = fmaxf(mean, 0.f);
                    }
                    float g = (v < 2) ? g0 : g1v;
                    oacc[mt][nt][v] = fmaf(g, ex, oacc[mt][nt][v]);
                }
            }
        }
    }

    float* ob = out + ((long)b * NN + m0) * 64;
    #pragma unroll
    for (int mt = 0; mt < 2; mt++) {
        int r = wm * 32 + mt * 16 + (lane >> 2);
        #pragma unroll
        for (int nt = 0; nt < 4; nt++) {
            int c = wn * 32 + nt * 8 + 2 * (lane & 3);
            *(float2*)(ob + (long)r * 64 + c)       = make_float2(oacc[mt][nt][0], oacc[mt][nt][1]);
            *(float2*)(ob + (long)(r + 8) * 64 + c) = make_float2(oacc[mt][nt][2], oacc[mt][nt][3]);
        }
    }
}

// ===========================================================================
// Launch
// ===========================================================================
extern "C" void kernel_launch(void* const* d_in, const int* in_sizes, int n_in,
                              void* d_out, int out_size) {
    const float* shift = (const float*)d_in[0];
    const float* A2    = (const float*)d_in[1];
    const float* feat  = (const float*)d_in[2];
    const float* W     = (const float*)d_in[3];
    const float* pi    = (const float*)d_in[4];
    const float* mu    = (const float*)d_in[5];
    const float* sigma = (const float*)d_in[6];
    float* out = (float*)d_out;

    float* scr = nullptr;
    cudaGetSymbolAddress((void**)&scr, g_scratch);

    __half* shift_h = (__half*)(scr + OFF_SHIFT_H);
    __half* a2_h    = (__half*)(scr + OFF_A2_H);
    __half* c1t     = (__half*)(scr + OFF_C1T);

    // conversions (both matrices, one launch)
    const int n4 = NN * NN / 4;
    convert_h_kernel<<<dim3((n4 + 255) / 256, 2), 256>>>(
        (const float4*)shift, (uint2*)shift_h,
        (const float4*)A2, (uint2*)a2_h, n4);

    // prep
    prep_mv_kernel<<<(KK * 64 * 64 + 255) / 256, 256>>>(W, mu, sigma);
    prep_gamma_kernel<<<BB * NN / 8, 256>>>(feat, mu, sigma, pi);
    trans_feat_kernel<<<dim3(NN / 32, 2, BB), dim3(32, 32)>>>(feat);

    // fused GEMMs + tail
    cudaFuncSetAttribute(mega_kernel,
                         cudaFuncAttributeMaxDynamicSharedMemorySize, SM_TOT);
    mega_kernel<<<dim3(NN / 128, BB), 256, SM_TOT>>>(shift_h, a2_h, c1t, out);
}

// round 14
// speedup vs baseline: 6.0488x; 1.1442x over previous
#include <cuda_runtime.h>
#include <cuda_fp16.h>
#include <cstdint>
#include <math.h>

// Problem constants
#define NN 4096
#define FF 64
#define OO 64
#define KK 5
#define BB 8

// ---------------------------------------------------------------------------
// Scratch layout (float offsets into g_scratch)
// ---------------------------------------------------------------------------
#define OFF_GAMMA   0L          // [B][4096][5] fp32            (163840)
#define OFF_WT      163840L     // fp16 [64o][64f] = W[f,o]     (2048)
#define OFF_W2T     165888L     // fp16 [64o][64f] = W[f,o]^2   (2048)
#define OFF_MU      167936L     // fp16 [5][64] mu              (160)
#define OFF_VA      168096L     // fp16 [5][64] exp(sigma)      (160)
#define OFF_SHIFT_H 168256L     // fp16 [4096][4096]            (8388608)
#define OFF_A2_H    8556864L    // fp16 [4096][4096]            (8388608)
#define OFF_C1T     16945472L   // fp16 [B][128][4096]          (2097152)
#define SCRATCH_TOTAL 19042624L

__device__ float g_scratch[SCRATCH_TOTAL];

// ===========================================================================
// PTX helpers
// ===========================================================================
__device__ __forceinline__ uint32_t smem_to_u32(const void* p) {
    uint32_t a;
    asm("{ .reg .u64 t; cvta.to.shared.u64 t, %1; cvt.u32.u64 %0, t; }"
        : "=r"(a) : "l"(p));
    return a;
}

__device__ __forceinline__ void cp16(uint32_t dst, const void* src) {
    asm volatile("cp.async.cg.shared.global [%0], [%1], 16;"
                 :: "r"(dst), "l"(src) : "memory");
}
#define CP_COMMIT() asm volatile("cp.async.commit_group;" ::: "memory")
#define CP_WAIT2()  asm volatile("cp.async.wait_group 2;" ::: "memory")
#define CP_WAIT1()  asm volatile("cp.async.wait_group 1;" ::: "memory")
#define CP_WAIT0()  asm volatile("cp.async.wait_group 0;" ::: "memory")

__device__ __forceinline__ void ldsm4(uint32_t* f, uint32_t addr) {
    asm volatile("ldmatrix.sync.aligned.m8n8.x4.shared.b16 {%0,%1,%2,%3}, [%4];"
                 : "=r"(f[0]), "=r"(f[1]), "=r"(f[2]), "=r"(f[3]) : "r"(addr));
}

__device__ __forceinline__ void mma_fp16(float* c, const uint32_t* a, const uint32_t* b) {
    asm volatile(
        "mma.sync.aligned.m16n8k16.row.col.f32.f16.f16.f32 "
        "{%0,%1,%2,%3}, {%4,%5,%6,%7}, {%8,%9}, {%0,%1,%2,%3};"
        : "+f"(c[0]), "+f"(c[1]), "+f"(c[2]), "+f"(c[3])
        : "r"(a[0]), "r"(a[1]), "r"(a[2]), "r"(a[3]), "r"(b[0]), "r"(b[1]));
}

__device__ __forceinline__ uint32_t hmul2u(uint32_t a, uint32_t b) {
    __half2 r = __hmul2(*reinterpret_cast<__half2*>(&a),
                        *reinterpret_cast<__half2*>(&b));
    return *reinterpret_cast<uint32_t*>(&r);
}

// SW128 swizzle for 128-byte rows
__device__ __forceinline__ uint32_t swz(int row, int kb) {
    return (uint32_t)(row * 128 + (kb ^ ((row & 7) << 4)));
}
__device__ __forceinline__ uint32_t lda_addr(uint32_t base, int lane, int r0, int kb) {
    int grp = lane >> 3;
    int row = r0 + (lane & 7) + ((grp & 1) << 3);
    int kb2 = kb + ((grp >> 1) << 4);
    return base + swz(row, kb2);
}
__device__ __forceinline__ uint32_t ldb_addr(uint32_t base, int lane, int n0, int kb) {
    int grp = lane >> 3;
    int row = n0 + (lane & 7) + ((grp >> 1) << 3);
    int kb2 = kb + ((grp & 1) << 4);
    return base + swz(row, kb2);
}

// ===========================================================================
// fp32 -> fp16 conversion (both big matrices; y selects matrix)
// ===========================================================================
__global__ void __launch_bounds__(256) convert_h_kernel(
    const float4* __restrict__ s0, uint2* __restrict__ d0,
    const float4* __restrict__ s1, uint2* __restrict__ d1, int n4)
{
    int i = blockIdx.x * 256 + threadIdx.x;
    if (i >= n4) return;
    const float4* src = blockIdx.y ? s1 : s0;
    uint2* dst = blockIdx.y ? d1 : d0;
    float4 v = src[i];
    __half2 h01 = __floats2half2_rn(v.x, v.y);
    __half2 h23 = __floats2half2_rn(v.z, v.w);
    uint2 o;
    o.x = *reinterpret_cast<uint32_t*>(&h01);
    o.y = *reinterpret_cast<uint32_t*>(&h23);
    dst[i] = o;
}

// ===========================================================================
// P0: Wt[o][f]=W[f,o], W2t[o][f]=W[f,o]^2, muh[k][f]=mu, vah[k][f]=exp(sig)
// ===========================================================================
__global__ void prep_consts_kernel(const float* __restrict__ W,
                                   const float* __restrict__ mu,
                                   const float* __restrict__ sigma) {
    int idx = blockIdx.x * 256 + threadIdx.x;
    __half* wt  = (__half*)(g_scratch + OFF_WT);
    __half* w2t = (__half*)(g_scratch + OFF_W2T);
    __half* muh = (__half*)(g_scratch + OFF_MU);
    __half* vah = (__half*)(g_scratch + OFF_VA);
    if (idx < 4096) {
        int o = idx >> 6, f = idx & 63;
        float w = W[f * 64 + o];
        wt[idx]  = __float2half(w);
        w2t[idx] = __float2half(w * w);
    } else if (idx < 4096 + 320) {
        int j = idx - 4096;
        muh[j] = __float2half(mu[j]);
        vah[j] = __float2half(expf(sigma[j]));
    }
}

// ===========================================================================
// P1 fused: per 32-row block: sanitize+transpose features -> C1T fp16,
//           and compute gamma (softmax responsibilities)
// ===========================================================================
__global__ void __launch_bounds__(1024) prep_feat_kernel(
    const float* __restrict__ feat, const float* __restrict__ mu,
    const float* __restrict__ sigma, const float* __restrict__ pi)
{
    __shared__ float mus[KK * 64];
    __shared__ float ivs[KK * 64];
    __shared__ float pis[KK];
    __shared__ __half t[128][34];

    int tx = threadIdx.x, ty = threadIdx.y;
    int tid = ty * 32 + tx;
    if (tid < KK * 64) { mus[tid] = mu[tid]; ivs[tid] = expf(-sigma[tid]); }
    if (tid < KK) pis[tid] = pi[tid];
    __syncthreads();

    int b = blockIdx.y;
    int m0 = blockIdx.x * 32;
    long row = (long)b * NN + m0 + ty;
    float v0 = feat[row * 64 + tx], v1 = feat[row * 64 + tx + 32];
    bool nm0 = isnan(v0), nm1 = isnan(v1);
    float f0 = nm0 ? 0.f : v0;
    float f1 = nm1 ? 0.f : v1;
    t[tx][ty]      = __float2half(f0);
    t[tx + 32][ty] = __float2half(f1);
    t[tx + 64][ty] = __float2half(nm0 ? 1.f : 0.f);
    t[tx + 96][ty] = __float2half(nm1 ? 1.f : 0.f);

    // gamma: warp == row ty, lanes == tx
    float lg[KK];
    #pragma unroll
    for (int k = 0; k < KK; k++) {
        float p = 0.f;
        if (!nm0) { float d = f0 - mus[k * 64 + tx];      p = fmaf(d * d, ivs[k * 64 + tx], p); }
        if (!nm1) { float d = f1 - mus[k * 64 + tx + 32]; p = fmaf(d * d, ivs[k * 64 + tx + 32], p); }
        #pragma unroll
        for (int off = 16; off > 0; off >>= 1) p += __shfl_xor_sync(0xffffffffu, p, off);
        lg[k] = pis[k] - 0.5f * p;
    }
    float mx = lg[0];
    #pragma unroll
    for (int k = 1; k < KK; k++) mx = fmaxf(mx, lg[k]);
    float e[KK], den = 0.f;
    #pragma unroll
    for (int k = 0; k < KK; k++) { e[k] = __expf(lg[k] - mx); den += e[k]; }
    if (tx == 0) {
        float inv = 1.f / den;
        #pragma unroll
        for (int k = 0; k < KK; k++) g_scratch[OFF_GAMMA + row * KK + k] = e[k] * inv;
    }
    __syncthreads();

    // write transposed: 2048 u32 = 128 rows x 16 m-pairs
    uint32_t* dst = (uint32_t*)(g_scratch + OFF_C1T);
    #pragma unroll
    for (int p = 0; p < 2; p++) {
        int i = tid + p * 1024;
        int c = i >> 4, mp = i & 15;
        uint32_t val = *(uint32_t*)&t[c][mp * 2];
        dst[((long)b * 128 + c) * (NN / 2) + (m0 >> 1) + mp] = val;
    }
}

// ===========================================================================
// MEGA kernel v2: 64-row tiles, 256 thr, occ 2, 3-stage pipeline.
//   mainloop: [U|S] = shift @ c1t^T (cols 0..127), T = A2 @ mask^T (cols 128..191)
//   tail: ux=U@Wt^T; per k: dx=(S*mu_k)@Wt^T, dc=(T*var_k)@W2t^T; gamma-mix
// ===========================================================================
#define STG_BYTES 32768         // AS 8K @0 | AA 8K @8192 | B 16K @16384
#define SM_TOT    98304         // 3 stages
// tail layout (valid after mainloop)
#define SM_U    0
#define SM_S    8192
#define SM_T    16384
#define SM_WT   24576
#define SM_W2T  32768
#define SM_G    40960
#define SM_MU   42240
#define SM_VA   42880

__global__ void __launch_bounds__(256, 2)
mega_kernel(const __half* __restrict__ Ash, const __half* __restrict__ Aa2,
            const __half* __restrict__ C1T, float* __restrict__ out)
{
    constexpr int BK = 64;
    constexpr int NC = NN / BK;

    extern __shared__ char smem[];
    uint32_t sbase = smem_to_u32(smem);
    const int tid = threadIdx.x, wid = tid >> 5, lane = tid & 31;
    const int wm = wid & 3, wn = wid >> 2;      // 16 rows x 96 cols per warp
    const int m0 = blockIdx.x * 64;
    const int b  = blockIdx.y;

    const __half* Bb = C1T + (long)b * (128L * NN);

    auto load_chunk = [&](int kc) {
        uint32_t st = sbase + (uint32_t)(kc % 3) * STG_BYTES;
        long gc = (long)kc * BK;
        #pragma unroll
        for (int p = 0; p < 2; p++) {
            int idx = tid + p * 256;
            int r = idx >> 3, c16 = idx & 7;
            cp16(st + swz(r, c16 * 16),        Ash + (long)(m0 + r) * NN + gc + c16 * 8);
            cp16(st + 8192 + swz(r, c16 * 16), Aa2 + (long)(m0 + r) * NN + gc + c16 * 8);
        }
        #pragma unroll
        for (int p = 0; p < 4; p++) {
            int idx = tid + p * 256;
            int r = idx >> 3, c16 = idx & 7;
            cp16(st + 16384 + swz(r, c16 * 16), Bb + (long)r * NN + gc + c16 * 8);
        }
        CP_COMMIT();
    };

    float acc[12][4] = {};

    load_chunk(0);
    load_chunk(1);

    for (int kc = 0; kc < NC; kc++) {
        if (kc + 2 < NC) load_chunk(kc + 2);
        if (kc + 2 < NC)      { CP_WAIT2(); }
        else if (kc + 1 < NC) { CP_WAIT1(); }
        else                  { CP_WAIT0(); }
        __syncthreads();

        uint32_t st = sbase + (uint32_t)(kc % 3) * STG_BYTES;
        #pragma unroll
        for (int ks = 0; ks < 4; ks++) {
            int kb = ks * 32;
            uint32_t af[4];
            ldsm4(af, lda_addr(st, lane, wm * 16, kb));          // shift A rows
            if (wn == 0) {
                uint32_t bf[24];
                #pragma unroll
                for (int p = 0; p < 6; p++)
                    ldsm4(&bf[p * 4], ldb_addr(st + 16384, lane, p * 16, kb));
                #pragma unroll
                for (int j = 0; j < 12; j++)
                    mma_fp16(acc[j], af, &bf[j * 2]);
            } else {
                uint32_t af2[4];
                ldsm4(af2, lda_addr(st + 8192, lane, wm * 16, kb));  // A2 rows
                uint32_t bf[16];                                      // B rows 64..127
                #pragma unroll
                for (int p = 0; p < 4; p++)
                    ldsm4(&bf[p * 4], ldb_addr(st + 16384, lane, 64 + p * 16, kb));
                // tiles 0..3 => cols 96..127 (S hi) : shift A, B rows 96..127 = frags 4..7
                #pragma unroll
                for (int j = 0; j < 4; j++)
                    mma_fp16(acc[j], af, &bf[(4 + j) * 2]);
                // tiles 4..11 => cols 128..191 (T) : A2, B rows 64..127 = frags 0..7
                #pragma unroll
                for (int j = 4; j < 12; j++)
                    mma_fp16(acc[j], af2, &bf[(j - 4) * 2]);
            }
        }
        __syncthreads();
    }

    // --------------------------------------------------------------
    // constants cp.async + fragment spill to SMEM (fp16)
    // --------------------------------------------------------------
    {
        const __half* wtg = (const __half*)(g_scratch + OFF_WT);
        const __half* w2g = (const __half*)(g_scratch + OFF_W2T);
        #pragma unroll
        for (int p = 0; p < 2; p++) {
            int i = tid + p * 256;
            int r = i >> 3, c = i & 7;
            cp16(sbase + SM_WT  + swz(r, c * 16), wtg + (long)i * 8);
            cp16(sbase + SM_W2T + swz(r, c * 16), w2g + (long)i * 8);
        }
        const char* gg = (const char*)(g_scratch + OFF_GAMMA + ((long)b * NN + m0) * KK);
        if (tid < 80) cp16(sbase + SM_G + tid * 16, gg + tid * 16);
        const char* mug = (const char*)(g_scratch + OFF_MU);
        const char* vag = (const char*)(g_scratch + OFF_VA);
        if (tid < 40) {
            cp16(sbase + SM_MU + tid * 16, mug + tid * 16);
            cp16(sbase + SM_VA + tid * 16, vag + tid * 16);
        }
        CP_COMMIT();
    }
    {
        int rl = lane >> 2;
        int q2 = 2 * (lane & 3);
        int r0 = wm * 16 + rl, r1 = r0 + 8;
        #pragma unroll
        for (int j = 0; j < 12; j++) {
            int c = wn * 96 + j * 8;
            uint32_t base = (c < 64) ? SM_U : (c < 128 ? SM_S : SM_T);
            int cc = (c < 64) ? c : (c < 128 ? c - 64 : c - 128);
            int col2 = (cc + q2) * 2;
            __half2 lo = __floats2half2_rn(acc[j][0], acc[j][1]);
            __half2 hi = __floats2half2_rn(acc[j][2], acc[j][3]);
            *(uint32_t*)(smem + base + r0 * 128 + (col2 ^ ((r0 & 7) << 4))) =
                *reinterpret_cast<uint32_t*>(&lo);
            *(uint32_t*)(smem + base + r1 * 128 + (col2 ^ ((r1 & 7) << 4))) =
                *reinterpret_cast<uint32_t*>(&hi);
        }
    }
    CP_WAIT0();
    __syncthreads();

    // --------------------------------------------------------------
    // Tail
    // --------------------------------------------------------------
    const int t4 = lane & 3;

    float ux[4][4] = {};
    #pragma unroll
    for (int ks = 0; ks < 4; ks++) {
        int kb = ks * 32;
        uint32_t uf[4];
        ldsm4(uf, lda_addr(sbase + SM_U, lane, wm * 16, kb));
        uint32_t wf[8];
        ldsm4(&wf[0], ldb_addr(sbase + SM_WT, lane, wn * 32, kb));
        ldsm4(&wf[4], ldb_addr(sbase + SM_WT, lane, wn * 32 + 16, kb));
        #pragma unroll
        for (int j = 0; j < 4; j++)
            mma_fp16(ux[j], uf, &wf[j * 2]);
    }

    float oacc[4][4] = {};
    const float* sg = (const float*)(smem + SM_G);

    #pragma unroll 1
    for (int k = 0; k < KK; k++) {
        float dx[4][4] = {};
        float dc[4][4] = {};
        #pragma unroll
        for (int ks = 0; ks < 4; ks++) {
            int kb = ks * 32;
            uint32_t sf[4], tf[4];
            ldsm4(sf, lda_addr(sbase + SM_S, lane, wm * 16, kb));
            ldsm4(tf, lda_addr(sbase + SM_T, lane, wm * 16, kb));
            uint32_t mu0 = *(uint32_t*)(smem + SM_MU + (k * 32 + ks * 8 + t4) * 4);
            uint32_t mu1 = *(uint32_t*)(smem + SM_MU + (k * 32 + ks * 8 + t4 + 4) * 4);
            uint32_t va0 = *(uint32_t*)(smem + SM_VA + (k * 32 + ks * 8 + t4) * 4);
            uint32_t va1 = *(uint32_t*)(smem + SM_VA + (k * 32 + ks * 8 + t4 + 4) * 4);
            sf[0] = hmul2u(sf[0], mu0); sf[1] = hmul2u(sf[1], mu0);
            sf[2] = hmul2u(sf[2], mu1); sf[3] = hmul2u(sf[3], mu1);
            tf[0] = hmul2u(tf[0], va0); tf[1] = hmul2u(tf[1], va0);
            tf[2] = hmul2u(tf[2], va1); tf[3] = hmul2u(tf[3], va1);
            uint32_t wf[8], w2f[8];
            ldsm4(&wf[0],  ldb_addr(sbase + SM_WT,  lane, wn * 32, kb));
            ldsm4(&wf[4],  ldb_addr(sbase + SM_WT,  lane, wn * 32 + 16, kb));
            ldsm4(&w2f[0], ldb_addr(sbase + SM_W2T, lane, wn * 32, kb));
            ldsm4(&w2f[4], ldb_addr(sbase + SM_W2T, lane, wn * 32 + 16, kb));
            #pragma unroll
            for (int j = 0; j < 4; j++) {
                mma_fp16(dx[j], sf, &wf[j * 2]);
                mma_fp16(dc[j], tf, &w2f[j * 2]);
            }
        }
        int rl0 = wm * 16 + (lane >> 2);
        float g0 = sg[rl0 * KK + k];
        float g1 = sg[(rl0 + 8) * KK + k];
        #pragma unroll
        for (int j = 0; j < 4; j++) {
            #pragma unroll
            for (int v = 0; v < 4; v++) {
                float mean = ux[j][v] + dx[j][v];
                float var  = dc[j][v];
                float sd = sqrtf(fmaxf(var, 0.f));
                float ex;
                if (sd > 0.f) {
                    float zz = mean / sd;
                    ex = mean * normcdff(zz)
                       + sd * __expf(-0.5f * zz * zz) * 0.3989422804014327f;
                } else {
                    ex = fmaxf(mean, 0.f);
                }
                float g = (v < 2) ? g0 : g1;
                oacc[j][v] = fmaf(g, ex, oacc[j][v]);
            }
        }
    }

    float* ob = out + ((long)b * NN + m0) * 64;
    {
        int r = wm * 16 + (lane >> 2);
        int q2 = 2 * (lane & 3);
        #pragma unroll
        for (int j = 0; j < 4; j++) {
            int c = wn * 32 + j * 8 + q2;
            *(float2*)(ob + (long)r * 64 + c)       = make_float2(oacc[j][0], oacc[j][1]);
            *(float2*)(ob + (long)(r + 8) * 64 + c) = make_float2(oacc[j][2], oacc[j][3]);
        }
    }
}

// ===========================================================================
// Launch
// ===========================================================================
extern "C" void kernel_launch(void* const* d_in, const int* in_sizes, int n_in,
                              void* d_out, int out_size) {
    const float* shift = (const float*)d_in[0];
    const float* A2    = (const float*)d_in[1];
    const float* feat  = (const float*)d_in[2];
    const float* W     = (const float*)d_in[3];
    const float* pi    = (const float*)d_in[4];
    const float* mu    = (const float*)d_in[5];
    const float* sigma = (const float*)d_in[6];
    float* out = (float*)d_out;

    float* scr = nullptr;
    cudaGetSymbolAddress((void**)&scr, g_scratch);

    __half* shift_h = (__half*)(scr + OFF_SHIFT_H);
    __half* a2_h    = (__half*)(scr + OFF_A2_H);
    __half* c1t     = (__half*)(scr + OFF_C1T);

    const int n4 = NN * NN / 4;
    convert_h_kernel<<<dim3((n4 + 255) / 256, 2), 256>>>(
        (const float4*)shift, (uint2*)shift_h,
        (const float4*)A2, (uint2*)a2_h, n4);

    prep_consts_kernel<<<(4096 + 320 + 255) / 256, 256>>>(W, mu, sigma);
    prep_feat_kernel<<<dim3(NN / 32, BB), dim3(32, 32)>>>(feat, mu, sigma, pi);

    cudaFuncSetAttribute(mega_kernel,
                         cudaFuncAttributeMaxDynamicSharedMemorySize, SM_TOT);
    mega_kernel<<<dim3(NN / 64, BB), 256, SM_TOT>>>(shift_h, a2_h, c1t, out);
}